// round 1
// baseline (speedup 1.0000x reference)
#include <cuda_runtime.h>
#include <math.h>

// ---------------------------------------------------------------------------
// DSFDecoder: B=16, C=128, H=W=64, OUT=64, CR=16, RE=8
// Pipeline:
//   per input s in {x1,x2}:
//     pool -> mlp(d1) -> wk1 ; t = relu(dw(x,wk1)+x)
//     pool(t) -> mlp(d2) -> wk2 ; ab[s] = dw(t,wk2)+t
//   fused = 1x1(concat(ab0,ab1), align_w)                      [16,128,64,64]
//   W_eff[sub] = up_w2 @ up_w1  (fold conv+pixelshuffle+1x1)
//   up = subpixel-conv3x3(fused, W_eff) -> d_out               [16,64,128,128]
//   tre = relu(conv3x3(up, re_w1))                             [16,8,128,128]
//   d_out += conv3x3(tre, re_w2)
// ---------------------------------------------------------------------------

#define PLANE 4096            // 64*64
#define CH    128
#define BATCH 16

__device__ float g_t[2][BATCH * CH * PLANE];      // relu(dsc1)
__device__ float g_ab[2][BATCH * CH * PLANE];     // dsc2 outputs
__device__ float g_fused[BATCH * CH * PLANE];
__device__ float g_weff[4 * 64 * 128 * 9];
__device__ float g_tre[BATCH * 8 * 128 * 128];
__device__ float g_pool[2][BATCH * CH];
__device__ float g_wk[2][BATCH * CH * 9];

// ---------------- pooling: mean over 64x64 plane ----------------
__global__ void pool_kernel(const float* __restrict__ x, int slot, int use_t) {
    const float* src = (use_t ? &g_t[slot][0] : x) + (size_t)blockIdx.x * PLANE;
    int tid = threadIdx.x;
    float s = 0.f;
    const float4* v = (const float4*)src;
    for (int i = tid; i < PLANE / 4; i += 256) {
        float4 q = v[i];
        s += q.x + q.y + q.z + q.w;
    }
    for (int off = 16; off; off >>= 1) s += __shfl_xor_sync(0xffffffffu, s, off);
    __shared__ float red[8];
    if ((tid & 31) == 0) red[tid >> 5] = s;
    __syncthreads();
    if (tid < 32) {
        float r = (tid < 8) ? red[tid] : 0.f;
        for (int off = 4; off; off >>= 1) r += __shfl_xor_sync(0xffffffffu, r, off);
        if (tid == 0) g_pool[slot][blockIdx.x] = r * (1.f / 4096.f);
    }
}

// ---------------- mlp: pooled -> gelu -> logits -> softmax(9) ----------------
__global__ void mlp_kernel(const float* __restrict__ w1, const float* __restrict__ w2,
                           int slot) {
    int b = blockIdx.x;          // 16 blocks, 128 threads
    int tid = threadIdx.x;
    __shared__ float sp[128], sh[16];
    sp[tid] = g_pool[slot][b * 128 + tid];
    __syncthreads();
    if (tid < 16) {
        float acc = 0.f;
        #pragma unroll 8
        for (int c = 0; c < 128; c++) acc += sp[c] * w1[tid * 128 + c];
        sh[tid] = 0.5f * acc * (1.f + erff(acc * 0.70710678118654752f));
    }
    __syncthreads();
    int c = tid;
    float lg[9];
    float mx = -1e30f;
    #pragma unroll
    for (int k = 0; k < 9; k++) {
        float acc = 0.f;
        #pragma unroll
        for (int r = 0; r < 16; r++) acc += sh[r] * w2[(c * 9 + k) * 16 + r];
        lg[k] = acc;
        mx = fmaxf(mx, acc);
    }
    float ss = 0.f;
    #pragma unroll
    for (int k = 0; k < 9; k++) { lg[k] = expf(lg[k] - mx); ss += lg[k]; }
    float inv = 1.f / ss;
    #pragma unroll
    for (int k = 0; k < 9; k++) g_wk[slot][(b * 128 + c) * 9 + k] = lg[k] * inv;
}

// ---------------- dsc apply: depthwise 3x3 (per-bc kernel) + residual ----------------
__global__ void dsc_kernel(const float* __restrict__ xext, int slot, int phase) {
    int bc = blockIdx.x;   // b*128 + c
    const float* src = phase ? &g_t[slot][(size_t)bc * PLANE]
                             : xext + (size_t)bc * PLANE;
    float* dst = phase ? &g_ab[slot][(size_t)bc * PLANE]
                       : &g_t[slot][(size_t)bc * PLANE];
    float wk[9];
    #pragma unroll
    for (int k = 0; k < 9; k++) wk[k] = g_wk[slot][bc * 9 + k];
    __shared__ float sp[64][64];
    int tid = threadIdx.x;
    for (int i = tid; i < PLANE; i += 256) sp[i >> 6][i & 63] = src[i];
    __syncthreads();
    for (int p = tid; p < PLANE; p += 256) {
        int h = p >> 6, w = p & 63;
        float acc = sp[h][w];   // residual
        #pragma unroll
        for (int kh = 0; kh < 3; kh++) {
            #pragma unroll
            for (int kw = 0; kw < 3; kw++) {
                int hh = h + kh - 1, ww = w + kw - 1;
                if ((unsigned)hh < 64u && (unsigned)ww < 64u)
                    acc += wk[kh * 3 + kw] * sp[hh][ww];
            }
        }
        dst[p] = phase ? acc : fmaxf(acc, 0.f);
    }
}

// ---------------- align: fused = concat(a,b) @ align_w^T (1x1 conv) ----------------
// grid (4 quarters, 8 ogroups, 16 b), 256 threads; thread: 4 pixels x 16 o
__global__ void __launch_bounds__(256) align_kernel(const float* __restrict__ w) {
    int b = blockIdx.z, og = blockIdx.y, q = blockIdx.x;
    int tid = threadIdx.x;
    __shared__ float sw[16][256];
    for (int i = tid; i < 4096; i += 256)
        sw[i >> 8][i & 255] = w[(og * 16 + (i >> 8)) * 256 + (i & 255)];
    __syncthreads();
    int pix = q * 1024 + tid * 4;
    const float* ap = &g_ab[0][(size_t)b * CH * PLANE];
    const float* bp = &g_ab[1][(size_t)b * CH * PLANE];
    float4 acc[16];
    #pragma unroll
    for (int oo = 0; oo < 16; oo++) acc[oo] = make_float4(0.f, 0.f, 0.f, 0.f);
    for (int c = 0; c < 128; c++) {
        float4 xv = *(const float4*)(ap + (size_t)c * PLANE + pix);
        #pragma unroll
        for (int oo = 0; oo < 16; oo++) {
            float wv = sw[oo][c];
            acc[oo].x += wv * xv.x; acc[oo].y += wv * xv.y;
            acc[oo].z += wv * xv.z; acc[oo].w += wv * xv.w;
        }
    }
    for (int c = 0; c < 128; c++) {
        float4 xv = *(const float4*)(bp + (size_t)c * PLANE + pix);
        #pragma unroll
        for (int oo = 0; oo < 16; oo++) {
            float wv = sw[oo][128 + c];
            acc[oo].x += wv * xv.x; acc[oo].y += wv * xv.y;
            acc[oo].z += wv * xv.z; acc[oo].w += wv * xv.w;
        }
    }
    #pragma unroll
    for (int oo = 0; oo < 16; oo++) {
        int o = og * 16 + oo;
        *(float4*)&g_fused[((size_t)b * CH + o) * PLANE + pix] = acc[oo];
    }
}

// ---------------- effective weights for fused conv+pixelshuffle+1x1 ----------------
// W_eff[sub][o][ci][t] = sum_c up_w2[o,c] * up_w1[c*4+sub][ci][t]
__global__ void weff_kernel(const float* __restrict__ w1, const float* __restrict__ w2) {
    int sub = blockIdx.x >> 7, ci = blockIdx.x & 127;   // 512 blocks, 64 threads
    __shared__ float s1[128 * 9];
    for (int i = threadIdx.x; i < 1152; i += 64) {
        int c = i / 9, t = i - c * 9;
        s1[i] = w1[((size_t)(c * 4 + sub) * 128 + ci) * 9 + t];
    }
    __syncthreads();
    int o = threadIdx.x;
    float acc[9] = {0.f, 0.f, 0.f, 0.f, 0.f, 0.f, 0.f, 0.f, 0.f};
    for (int c = 0; c < 128; c++) {
        float wv = w2[o * 128 + c];
        #pragma unroll
        for (int t = 0; t < 9; t++) acc[t] += wv * s1[c * 9 + t];
    }
    #pragma unroll
    for (int t = 0; t < 9; t++)
        g_weff[((size_t)(sub * 64 + o) * 128 + ci) * 9 + t] = acc[t];
}

// ---------------- main conv: up = subpixel conv3x3(fused, W_eff) -> d_out ----------------
// grid (16 rowgroups, 4 subs, 16 b); 256 threads; thread: 8 pixels x 8 outputs
__global__ void __launch_bounds__(256, 2) upconv_kernel(float* __restrict__ out) {
    int b = blockIdx.z, sub = blockIdx.y, rg = blockIdx.x;
    int tid = threadIdx.x;
    int nt = tid & 7;          // o = nt*8 .. nt*8+7
    int mt = tid >> 3;         // 0..31 : row = mt>>3, colbase = (mt&7)*8
    int row0 = rg * 4;
    __shared__ float sIn[8][6][66];
    __shared__ float sW[8][9][64];
    float acc[8][8];
    #pragma unroll
    for (int p = 0; p < 8; p++)
        #pragma unroll
        for (int o = 0; o < 8; o++) acc[p][o] = 0.f;

    const float* fb = g_fused + (size_t)b * CH * PLANE;
    const float* wb = g_weff + (size_t)sub * 64 * 128 * 9;
    int r = mt >> 3, cb = (mt & 7) * 8;

    for (int cc = 0; cc < 128; cc += 8) {
        __syncthreads();
        for (int i = tid; i < 8 * 6 * 66; i += 256) {
            int c = i / 396, rem = i - c * 396;
            int rr = rem / 66, x = rem - rr * 66;
            int gr = row0 + rr - 1, gx = x - 1;
            float v = 0.f;
            if ((unsigned)gr < 64u && (unsigned)gx < 64u)
                v = fb[(size_t)(cc + c) * PLANE + gr * 64 + gx];
            sIn[c][rr][x] = v;
        }
        for (int i = tid; i < 8 * 9 * 64; i += 256) {
            int c = i / 576, rem = i - c * 576;
            int t = rem >> 6, o = rem & 63;
            sW[c][t][o] = wb[((size_t)o * 128 + cc + c) * 9 + t];
        }
        __syncthreads();
        #pragma unroll
        for (int c = 0; c < 8; c++) {
            #pragma unroll
            for (int t = 0; t < 9; t++) {
                const int kh = t / 3, kw = t - kh * 3;
                float wv[8], av[8];
                const float* wp = &sW[c][t][nt * 8];
                *(float4*)&wv[0] = *(const float4*)wp;
                *(float4*)&wv[4] = *(const float4*)(wp + 4);
                const float* ip = &sIn[c][r + kh][cb + kw];
                #pragma unroll
                for (int p = 0; p < 8; p++) av[p] = ip[p];
                #pragma unroll
                for (int p = 0; p < 8; p++)
                    #pragma unroll
                    for (int o = 0; o < 8; o++)
                        acc[p][o] += av[p] * wv[o];
            }
        }
    }
    int y = 2 * (row0 + r) + (sub >> 1);
    int r2 = sub & 1;
    #pragma unroll
    for (int o8 = 0; o8 < 8; o8++) {
        int o = nt * 8 + o8;
        float* op = out + ((size_t)(b * 64 + o) * 128 + y) * 128;
        #pragma unroll
        for (int p = 0; p < 8; p++)
            op[2 * (cb + p) + r2] = acc[p][o8];
    }
}

// ---------------- refine conv1: tre = relu(conv3x3(up, re_w1)) ----------------
// grid (8 rowgroups of 16, 16 b); 256 threads; thread: 8 pixels x 8 r-channels
__global__ void __launch_bounds__(256, 2) reconv1_kernel(const float* __restrict__ up,
                                                         const float* __restrict__ w) {
    int b = blockIdx.y, rg = blockIdx.x;
    int tid = threadIdx.x;
    int row = tid >> 4;          // 0..15
    int cb = (tid & 15) * 8;     // 0..120
    int rowbase = rg * 16;
    __shared__ float sW1[64][9][8];   // [c][t][r]
    __shared__ float sU[2][18][130];
    for (int i = tid; i < 64 * 9 * 8; i += 256) {
        int c = i / 72, rem = i - c * 72;
        int t = rem >> 3, rr = rem & 7;
        sW1[c][t][rr] = w[((size_t)rr * 64 + c) * 9 + t];
    }
    float acc[8][8];
    #pragma unroll
    for (int p = 0; p < 8; p++)
        #pragma unroll
        for (int rr = 0; rr < 8; rr++) acc[p][rr] = 0.f;

    const float* ub = up + (size_t)b * 64 * 128 * 128;
    for (int cc = 0; cc < 64; cc += 2) {
        __syncthreads();
        for (int i = tid; i < 2 * 18 * 130; i += 256) {
            int c = i / 2340, rem = i - c * 2340;
            int rr = rem / 130, x = rem - rr * 130;
            int gy = rowbase + rr - 1, gx = x - 1;
            float v = 0.f;
            if ((unsigned)gy < 128u && (unsigned)gx < 128u)
                v = ub[(size_t)(cc + c) * 16384 + gy * 128 + gx];
            sU[c][rr][x] = v;
        }
        __syncthreads();
        #pragma unroll
        for (int c = 0; c < 2; c++) {
            #pragma unroll
            for (int t = 0; t < 9; t++) {
                const int kh = t / 3, kw = t - kh * 3;
                float wv[8], av[8];
                *(float4*)&wv[0] = *(const float4*)&sW1[cc + c][t][0];
                *(float4*)&wv[4] = *(const float4*)&sW1[cc + c][t][4];
                const float* ip = &sU[c][row + kh][cb + kw];
                #pragma unroll
                for (int p = 0; p < 8; p++) av[p] = ip[p];
                #pragma unroll
                for (int p = 0; p < 8; p++)
                    #pragma unroll
                    for (int rr = 0; rr < 8; rr++)
                        acc[p][rr] += av[p] * wv[rr];
            }
        }
    }
    int y = rowbase + row;
    #pragma unroll
    for (int rr = 0; rr < 8; rr++) {
        float* tp = &g_tre[((size_t)(b * 8 + rr) * 128 + y) * 128 + cb];
        #pragma unroll
        for (int p = 0; p < 8; p++) tp[p] = fmaxf(acc[p][rr], 0.f);
    }
}

// ---------------- refine conv2 + residual add: d_out += conv3x3(tre, re_w2) ----------------
// grid (64 rowgroups of 2, 16 b); 256 threads; thread: 8 pixels x 8 o
__global__ void __launch_bounds__(256, 2) reconv2_kernel(const float* __restrict__ w,
                                                         float* __restrict__ out) {
    int b = blockIdx.y, rg = blockIdx.x;
    int tid = threadIdx.x;
    int nt = tid & 7;            // o = nt*8..+7
    int mt = tid >> 3;           // 0..31: row=mt>>4 (0..1), cb=(mt&15)*8
    int row = mt >> 4, cb = (mt & 15) * 8;
    int rowbase = rg * 2;
    __shared__ float sW2[8][9][64];   // [r][t][o]
    __shared__ float sT[8][4][130];
    for (int i = tid; i < 8 * 9 * 64; i += 256) {
        int rr = i / 576, rem = i - rr * 576;
        int t = rem >> 6, o = rem & 63;
        sW2[rr][t][o] = w[((size_t)o * 8 + rr) * 9 + t];
    }
    for (int i = tid; i < 8 * 4 * 130; i += 256) {
        int c = i / 520, rem = i - c * 520;
        int rr = rem / 130, x = rem - rr * 130;
        int gy = rowbase + rr - 1, gx = x - 1;
        float v = 0.f;
        if ((unsigned)gy < 128u && (unsigned)gx < 128u)
            v = g_tre[((size_t)(b * 8 + c) * 128 + gy) * 128 + gx];
        sT[c][rr][x] = v;
    }
    __syncthreads();
    float acc[8][8];
    #pragma unroll
    for (int p = 0; p < 8; p++)
        #pragma unroll
        for (int o = 0; o < 8; o++) acc[p][o] = 0.f;
    #pragma unroll
    for (int rr = 0; rr < 8; rr++) {
        #pragma unroll
        for (int t = 0; t < 9; t++) {
            const int kh = t / 3, kw = t - kh * 3;
            float wv[8], av[8];
            const float* wp = &sW2[rr][t][nt * 8];
            *(float4*)&wv[0] = *(const float4*)wp;
            *(float4*)&wv[4] = *(const float4*)(wp + 4);
            const float* ip = &sT[rr][row + kh][cb + kw];
            #pragma unroll
            for (int p = 0; p < 8; p++) av[p] = ip[p];
            #pragma unroll
            for (int p = 0; p < 8; p++)
                #pragma unroll
                for (int o = 0; o < 8; o++)
                    acc[p][o] += av[p] * wv[o];
        }
    }
    int y = rowbase + row;
    #pragma unroll
    for (int o8 = 0; o8 < 8; o8++) {
        int o = nt * 8 + o8;
        float* op = out + ((size_t)(b * 64 + o) * 128 + y) * 128 + cb;
        #pragma unroll
        for (int p = 0; p < 8; p++) op[p] += acc[p][o8];
    }
}

// ---------------------------------------------------------------------------
extern "C" void kernel_launch(void* const* d_in, const int* in_sizes, int n_in,
                              void* d_out, int out_size) {
    const float* x1    = (const float*)d_in[0];
    const float* x2    = (const float*)d_in[1];
    const float* d1_w1 = (const float*)d_in[2];
    const float* d1_w2 = (const float*)d_in[3];
    const float* d2_w1 = (const float*)d_in[4];
    const float* d2_w2 = (const float*)d_in[5];
    const float* align_w = (const float*)d_in[6];
    const float* up_w1 = (const float*)d_in[7];
    const float* up_w2 = (const float*)d_in[8];
    const float* re_w1 = (const float*)d_in[9];
    const float* re_w2 = (const float*)d_in[10];
    float* out = (float*)d_out;

    // independent of data path: effective weights
    weff_kernel<<<512, 64>>>(up_w1, up_w2);

    // dynamic block, both inputs
    pool_kernel<<<2048, 256>>>(x1, 0, 0);
    pool_kernel<<<2048, 256>>>(x2, 1, 0);
    mlp_kernel<<<16, 128>>>(d1_w1, d1_w2, 0);
    mlp_kernel<<<16, 128>>>(d1_w1, d1_w2, 1);
    dsc_kernel<<<2048, 256>>>(x1, 0, 0);
    dsc_kernel<<<2048, 256>>>(x2, 1, 0);
    pool_kernel<<<2048, 256>>>(nullptr, 0, 1);
    pool_kernel<<<2048, 256>>>(nullptr, 1, 1);
    mlp_kernel<<<16, 128>>>(d2_w1, d2_w2, 0);
    mlp_kernel<<<16, 128>>>(d2_w1, d2_w2, 1);
    dsc_kernel<<<2048, 256>>>(nullptr, 0, 1);
    dsc_kernel<<<2048, 256>>>(nullptr, 1, 1);

    // fuse + upsample
    align_kernel<<<dim3(4, 8, 16), 256>>>(align_w);
    upconv_kernel<<<dim3(16, 4, 16), 256>>>(out);

    // refine + residual
    reconv1_kernel<<<dim3(8, 16), 256>>>(out, re_w1);
    reconv2_kernel<<<dim3(64, 16), 256>>>(re_w2, out);
}

// round 2
// speedup vs baseline: 1.3202x; 1.3202x over previous
#include <cuda_runtime.h>
#include <math.h>

// ---------------------------------------------------------------------------
// DSFDecoder: B=16, C=128, H=W=64, OUT=64, CR=16, RE=8
// FFMA2 (fma.rn.f32x2) packed-pair version.
// ---------------------------------------------------------------------------

#define PLANE 4096            // 64*64
#define CH    128
#define BATCH 16

typedef unsigned long long ull;

__device__ __forceinline__ void ffma2(ull& d, ull a, ull b) {
    asm("fma.rn.f32x2 %0, %1, %2, %0;" : "+l"(d) : "l"(a), "l"(b));
}
__device__ __forceinline__ ull splat2(float v) {
    ull r; asm("mov.b64 %0, {%1, %1};" : "=l"(r) : "f"(v)); return r;
}
__device__ __forceinline__ float2 unpk(ull v) {
    float2 f; asm("mov.b64 {%0, %1}, %2;" : "=f"(f.x), "=f"(f.y) : "l"(v)); return f;
}

__device__ float g_t[2][BATCH * CH * PLANE];      // relu(dsc1)
__device__ float g_ab[2][BATCH * CH * PLANE];     // dsc2 outputs
__device__ float g_fused[BATCH * CH * PLANE];
__device__ float g_weff[4 * 64 * 128 * 9];
__device__ float g_tre[BATCH * 8 * 128 * 128];
__device__ float g_pool[2][BATCH * CH];
__device__ float g_wk[2][BATCH * CH * 9];

// ---------------- pooling over x1/x2: mean over 64x64 plane ----------------
__global__ void pool_kernel(const float* __restrict__ x1, const float* __restrict__ x2) {
    int slot = blockIdx.x >> 11;
    int bc = blockIdx.x & 2047;
    const float* src = (slot ? x2 : x1) + (size_t)bc * PLANE;
    int tid = threadIdx.x;
    float s = 0.f;
    const float4* v = (const float4*)src;
    for (int i = tid; i < PLANE / 4; i += 256) {
        float4 q = v[i];
        s += q.x + q.y + q.z + q.w;
    }
    for (int off = 16; off; off >>= 1) s += __shfl_xor_sync(0xffffffffu, s, off);
    __shared__ float red[8];
    if ((tid & 31) == 0) red[tid >> 5] = s;
    __syncthreads();
    if (tid < 32) {
        float r = (tid < 8) ? red[tid] : 0.f;
        for (int off = 4; off; off >>= 1) r += __shfl_xor_sync(0xffffffffu, r, off);
        if (tid == 0) g_pool[slot][bc] = r * (1.f / 4096.f);
    }
}

// ---------------- mlp: pooled -> gelu -> logits -> softmax(9), both slots ----------------
__global__ void mlp_kernel(const float* __restrict__ w1, const float* __restrict__ w2) {
    int slot = blockIdx.x >> 4;
    int b = blockIdx.x & 15;
    int tid = threadIdx.x;
    __shared__ float sp[128], sh[16];
    sp[tid] = g_pool[slot][b * 128 + tid];
    __syncthreads();
    if (tid < 16) {
        float acc = 0.f;
        #pragma unroll 8
        for (int c = 0; c < 128; c++) acc += sp[c] * w1[tid * 128 + c];
        sh[tid] = 0.5f * acc * (1.f + erff(acc * 0.70710678118654752f));
    }
    __syncthreads();
    int c = tid;
    float lg[9];
    float mx = -1e30f;
    #pragma unroll
    for (int k = 0; k < 9; k++) {
        float acc = 0.f;
        #pragma unroll
        for (int r = 0; r < 16; r++) acc += sh[r] * w2[(c * 9 + k) * 16 + r];
        lg[k] = acc;
        mx = fmaxf(mx, acc);
    }
    float ss = 0.f;
    #pragma unroll
    for (int k = 0; k < 9; k++) { lg[k] = expf(lg[k] - mx); ss += lg[k]; }
    float inv = 1.f / ss;
    #pragma unroll
    for (int k = 0; k < 9; k++) g_wk[slot][(b * 128 + c) * 9 + k] = lg[k] * inv;
}

// ---------------- dsc apply: depthwise 3x3 + residual (+fused pool on phase 0) -------
__global__ void dsc_kernel(const float* __restrict__ x1, const float* __restrict__ x2,
                           int phase) {
    int slot = blockIdx.x >> 11;
    int bc = blockIdx.x & 2047;
    const float* xext = slot ? x2 : x1;
    const float* src = phase ? &g_t[slot][(size_t)bc * PLANE]
                             : xext + (size_t)bc * PLANE;
    float* dst = phase ? &g_ab[slot][(size_t)bc * PLANE]
                       : &g_t[slot][(size_t)bc * PLANE];
    float wk[9];
    #pragma unroll
    for (int k = 0; k < 9; k++) wk[k] = g_wk[slot][bc * 9 + k];
    __shared__ float sp[64][64];
    int tid = threadIdx.x;
    for (int i = tid; i < PLANE; i += 256) sp[i >> 6][i & 63] = src[i];
    __syncthreads();
    float psum = 0.f;
    for (int p = tid; p < PLANE; p += 256) {
        int h = p >> 6, w = p & 63;
        float acc = sp[h][w];   // residual
        #pragma unroll
        for (int kh = 0; kh < 3; kh++) {
            #pragma unroll
            for (int kw = 0; kw < 3; kw++) {
                int hh = h + kh - 1, ww = w + kw - 1;
                if ((unsigned)hh < 64u && (unsigned)ww < 64u)
                    acc += wk[kh * 3 + kw] * sp[hh][ww];
            }
        }
        if (phase) {
            dst[p] = acc;
        } else {
            float rv = fmaxf(acc, 0.f);
            dst[p] = rv;
            psum += rv;
        }
    }
    if (!phase) {   // fused AdaptiveAvgPool of t for the second MLP
        for (int off = 16; off; off >>= 1) psum += __shfl_xor_sync(0xffffffffu, psum, off);
        __shared__ float red[8];
        if ((tid & 31) == 0) red[tid >> 5] = psum;
        __syncthreads();
        if (tid < 32) {
            float r = (tid < 8) ? red[tid] : 0.f;
            for (int off = 4; off; off >>= 1) r += __shfl_xor_sync(0xffffffffu, r, off);
            if (tid == 0) g_pool[slot][bc] = r * (1.f / 4096.f);
        }
    }
}

// ---------------- align: fused = concat(a,b) @ align_w^T (1x1 conv), FFMA2 --------
// grid (4 quarters, 8 ogroups, 16 b); thread: 4 pixels x 16 o (8 o-pairs)
__global__ void __launch_bounds__(256, 2) align_kernel(const float* __restrict__ w) {
    int b = blockIdx.z, og = blockIdx.y, q = blockIdx.x;
    int tid = threadIdx.x;
    __shared__ float sw_s[256][16];
    for (int i = tid; i < 4096; i += 256) {
        int c = i >> 4, oo = i & 15;
        sw_s[c][oo] = w[(og * 16 + oo) * 256 + c];
    }
    __syncthreads();
    int pix = q * 1024 + tid * 4;
    const float* ap = &g_ab[0][(size_t)b * CH * PLANE] + pix;
    const float* bp = &g_ab[1][(size_t)b * CH * PLANE] + pix;
    ull acc2[8][4];
    #pragma unroll
    for (int jo = 0; jo < 8; jo++)
        #pragma unroll
        for (int p = 0; p < 4; p++) acc2[jo][p] = 0ull;
    for (int c = 0; c < 128; c++) {
        float4 xv = *(const float4*)(ap + (size_t)c * PLANE);
        ull s0 = splat2(xv.x), s1 = splat2(xv.y), s2 = splat2(xv.z), s3 = splat2(xv.w);
        const ull* wp = (const ull*)&sw_s[c][0];
        #pragma unroll
        for (int jo = 0; jo < 8; jo++) {
            ull wv = wp[jo];
            ffma2(acc2[jo][0], s0, wv);
            ffma2(acc2[jo][1], s1, wv);
            ffma2(acc2[jo][2], s2, wv);
            ffma2(acc2[jo][3], s3, wv);
        }
    }
    for (int c = 0; c < 128; c++) {
        float4 xv = *(const float4*)(bp + (size_t)c * PLANE);
        ull s0 = splat2(xv.x), s1 = splat2(xv.y), s2 = splat2(xv.z), s3 = splat2(xv.w);
        const ull* wp = (const ull*)&sw_s[128 + c][0];
        #pragma unroll
        for (int jo = 0; jo < 8; jo++) {
            ull wv = wp[jo];
            ffma2(acc2[jo][0], s0, wv);
            ffma2(acc2[jo][1], s1, wv);
            ffma2(acc2[jo][2], s2, wv);
            ffma2(acc2[jo][3], s3, wv);
        }
    }
    #pragma unroll
    for (int jo = 0; jo < 8; jo++) {
        int o = og * 16 + 2 * jo;
        float* f0 = &g_fused[((size_t)b * CH + o) * PLANE + pix];
        float* f1 = f0 + PLANE;
        #pragma unroll
        for (int p = 0; p < 4; p++) {
            float2 v = unpk(acc2[jo][p]);
            f0[p] = v.x;
            f1[p] = v.y;
        }
    }
}

// ---------------- effective weights: W_eff[sub][o][ci][t] = sum_c up_w2[o,c]*up_w1[4c+sub][ci][t]
__global__ void weff_kernel(const float* __restrict__ w1, const float* __restrict__ w2) {
    int sub = blockIdx.x >> 7, ci = blockIdx.x & 127;   // 512 blocks, 64 threads
    __shared__ float s1[128 * 9];
    for (int i = threadIdx.x; i < 1152; i += 64) {
        int c = i / 9, t = i - c * 9;
        s1[i] = w1[((size_t)(c * 4 + sub) * 128 + ci) * 9 + t];
    }
    __syncthreads();
    int o = threadIdx.x;
    float acc[9] = {0.f, 0.f, 0.f, 0.f, 0.f, 0.f, 0.f, 0.f, 0.f};
    for (int c = 0; c < 128; c++) {
        float wv = w2[o * 128 + c];
        #pragma unroll
        for (int t = 0; t < 9; t++) acc[t] += wv * s1[c * 9 + t];
    }
    #pragma unroll
    for (int t = 0; t < 9; t++)
        g_weff[((size_t)(sub * 64 + o) * 128 + ci) * 9 + t] = acc[t];
}

// ---------------- main conv: up = subpixel conv3x3(fused, W_eff) -> d_out, FFMA2 ----
// grid (16 rowgroups, 4 subs, 16 b); 256 thr; thread: 8 pixels x 8 outputs (4 o-pairs)
__global__ void __launch_bounds__(256, 2) upconv_kernel(float* __restrict__ out) {
    int b = blockIdx.z, sub = blockIdx.y, rg = blockIdx.x;
    int tid = threadIdx.x;
    int nt = tid & 7;          // o = nt*8 .. nt*8+7
    int mt = tid >> 3;         // row = mt>>3, colbase = (mt&7)*8
    int row0 = rg * 4;
    __shared__ float sIn[8][6][68];
    __shared__ float sW[8][9][64];
    ull acc2[8][4];
    #pragma unroll
    for (int p = 0; p < 8; p++)
        #pragma unroll
        for (int k = 0; k < 4; k++) acc2[p][k] = 0ull;

    const float* fb = g_fused + (size_t)b * CH * PLANE;
    const float* wb = g_weff + (size_t)sub * 64 * 128 * 9;
    int r = mt >> 3, cb = (mt & 7) * 8;

    for (int cc = 0; cc < 128; cc += 8) {
        __syncthreads();
        for (int i = tid; i < 8 * 6 * 68; i += 256) {
            int c = i / 408, rem = i - c * 408;
            int rr = rem / 68, x = rem - rr * 68;
            int gr = row0 + rr - 1, gx = x - 1;
            float v = 0.f;
            if ((unsigned)gr < 64u && (unsigned)gx < 64u)
                v = fb[(size_t)(cc + c) * PLANE + gr * 64 + gx];
            sIn[c][rr][x] = v;
        }
        for (int i = tid; i < 8 * 9 * 64; i += 256) {
            int c = i / 576, rem = i - c * 576;
            int t = rem >> 6, o = rem & 63;
            sW[c][t][o] = wb[((size_t)o * 128 + cc + c) * 9 + t];
        }
        __syncthreads();
        for (int c = 0; c < 8; c++) {
            #pragma unroll
            for (int kh = 0; kh < 3; kh++) {
                const float4* ip4 = (const float4*)&sIn[c][r + kh][cb];
                float4 q0 = ip4[0], q1 = ip4[1], q2 = ip4[2];
                ull s[10];
                s[0] = splat2(q0.x); s[1] = splat2(q0.y); s[2] = splat2(q0.z); s[3] = splat2(q0.w);
                s[4] = splat2(q1.x); s[5] = splat2(q1.y); s[6] = splat2(q1.z); s[7] = splat2(q1.w);
                s[8] = splat2(q2.x); s[9] = splat2(q2.y);
                #pragma unroll
                for (int kw = 0; kw < 3; kw++) {
                    const ull* wp = (const ull*)&sW[c][kh * 3 + kw][nt * 8];
                    ull w0 = wp[0], w1 = wp[1], w2 = wp[2], w3 = wp[3];
                    #pragma unroll
                    for (int p = 0; p < 8; p++) {
                        ffma2(acc2[p][0], s[kw + p], w0);
                        ffma2(acc2[p][1], s[kw + p], w1);
                        ffma2(acc2[p][2], s[kw + p], w2);
                        ffma2(acc2[p][3], s[kw + p], w3);
                    }
                }
            }
        }
    }
    int y = 2 * (row0 + r) + (sub >> 1);
    int r2 = sub & 1;
    #pragma unroll
    for (int k = 0; k < 4; k++) {
        int o = nt * 8 + 2 * k;
        float* op0 = out + ((size_t)(b * 64 + o) * 128 + y) * 128;
        float* op1 = op0 + 128 * 128;
        #pragma unroll
        for (int p = 0; p < 8; p++) {
            float2 v = unpk(acc2[p][k]);
            op0[2 * (cb + p) + r2] = v.x;
            op1[2 * (cb + p) + r2] = v.y;
        }
    }
}

// ---------------- refine conv1: tre = relu(conv3x3(up, re_w1)), FFMA2 ----------------
// grid (8 rowgroups of 16, 16 b); thread: 8 pixels x 8 r-channels (4 r-pairs)
__global__ void __launch_bounds__(256, 2) reconv1_kernel(const float* __restrict__ up,
                                                         const float* __restrict__ w) {
    int b = blockIdx.y, rg = blockIdx.x;
    int tid = threadIdx.x;
    int row = tid >> 4;          // 0..15
    int cb = (tid & 15) * 8;     // 0..120
    int rowbase = rg * 16;
    __shared__ float sW1[64][9][8];   // [c][t][r], r innermost
    __shared__ float sU[2][18][132];
    for (int i = tid; i < 64 * 9 * 8; i += 256) {
        int c = i / 72, rem = i - c * 72;
        int t = rem >> 3, rr = rem & 7;
        sW1[c][t][rr] = w[((size_t)rr * 64 + c) * 9 + t];
    }
    ull acc2[8][4];
    #pragma unroll
    for (int p = 0; p < 8; p++)
        #pragma unroll
        for (int k = 0; k < 4; k++) acc2[p][k] = 0ull;

    const float* ub = up + (size_t)b * 64 * 128 * 128;
    for (int cc = 0; cc < 64; cc += 2) {
        __syncthreads();
        for (int i = tid; i < 2 * 18 * 132; i += 256) {
            int c = i / 2376, rem = i - c * 2376;
            int rr = rem / 132, x = rem - rr * 132;
            int gy = rowbase + rr - 1, gx = x - 1;
            float v = 0.f;
            if ((unsigned)gy < 128u && (unsigned)gx < 128u)
                v = ub[(size_t)(cc + c) * 16384 + gy * 128 + gx];
            sU[c][rr][x] = v;
        }
        __syncthreads();
        #pragma unroll
        for (int c = 0; c < 2; c++) {
            #pragma unroll
            for (int kh = 0; kh < 3; kh++) {
                const float4* ip4 = (const float4*)&sU[c][row + kh][cb];
                float4 q0 = ip4[0], q1 = ip4[1], q2 = ip4[2];
                ull s[10];
                s[0] = splat2(q0.x); s[1] = splat2(q0.y); s[2] = splat2(q0.z); s[3] = splat2(q0.w);
                s[4] = splat2(q1.x); s[5] = splat2(q1.y); s[6] = splat2(q1.z); s[7] = splat2(q1.w);
                s[8] = splat2(q2.x); s[9] = splat2(q2.y);
                #pragma unroll
                for (int kw = 0; kw < 3; kw++) {
                    const ull* wp = (const ull*)&sW1[cc + c][kh * 3 + kw][0];
                    ull w0 = wp[0], w1 = wp[1], w2 = wp[2], w3 = wp[3];
                    #pragma unroll
                    for (int p = 0; p < 8; p++) {
                        ffma2(acc2[p][0], s[kw + p], w0);
                        ffma2(acc2[p][1], s[kw + p], w1);
                        ffma2(acc2[p][2], s[kw + p], w2);
                        ffma2(acc2[p][3], s[kw + p], w3);
                    }
                }
            }
        }
    }
    int y = rowbase + row;
    #pragma unroll
    for (int k = 0; k < 4; k++) {
        int rr = 2 * k;
        float* t0 = &g_tre[((size_t)(b * 8 + rr) * 128 + y) * 128 + cb];
        float* t1 = t0 + 128 * 128;
        #pragma unroll
        for (int p = 0; p < 8; p++) {
            float2 v = unpk(acc2[p][k]);
            t0[p] = fmaxf(v.x, 0.f);
            t1[p] = fmaxf(v.y, 0.f);
        }
    }
}

// ---------------- refine conv2 + residual: d_out += conv3x3(tre, re_w2), FFMA2 -------
// grid (64 rowgroups of 2, 16 b); thread: 8 pixels x 8 o (4 o-pairs)
__global__ void __launch_bounds__(256, 2) reconv2_kernel(const float* __restrict__ w,
                                                         float* __restrict__ out) {
    int b = blockIdx.y, rg = blockIdx.x;
    int tid = threadIdx.x;
    int nt = tid & 7;            // o = nt*8..+7
    int mt = tid >> 3;
    int row = mt >> 4, cb = (mt & 15) * 8;
    int rowbase = rg * 2;
    __shared__ float sW2[8][9][64];   // [r][t][o], o innermost
    __shared__ float sT[8][4][132];
    for (int i = tid; i < 8 * 9 * 64; i += 256) {
        int rr = i / 576, rem = i - rr * 576;
        int t = rem >> 6, o = rem & 63;
        sW2[rr][t][o] = w[((size_t)o * 8 + rr) * 9 + t];
    }
    for (int i = tid; i < 8 * 4 * 132; i += 256) {
        int c = i / 528, rem = i - c * 528;
        int rr = rem / 132, x = rem - rr * 132;
        int gy = rowbase + rr - 1, gx = x - 1;
        float v = 0.f;
        if ((unsigned)gy < 128u && (unsigned)gx < 128u)
            v = g_tre[((size_t)(b * 8 + c) * 128 + gy) * 128 + gx];
        sT[c][rr][x] = v;
    }
    __syncthreads();
    ull acc2[8][4];
    #pragma unroll
    for (int p = 0; p < 8; p++)
        #pragma unroll
        for (int k = 0; k < 4; k++) acc2[p][k] = 0ull;
    #pragma unroll
    for (int rr = 0; rr < 8; rr++) {
        #pragma unroll
        for (int kh = 0; kh < 3; kh++) {
            const float4* ip4 = (const float4*)&sT[rr][row + kh][cb];
            float4 q0 = ip4[0], q1 = ip4[1], q2 = ip4[2];
            ull s[10];
            s[0] = splat2(q0.x); s[1] = splat2(q0.y); s[2] = splat2(q0.z); s[3] = splat2(q0.w);
            s[4] = splat2(q1.x); s[5] = splat2(q1.y); s[6] = splat2(q1.z); s[7] = splat2(q1.w);
            s[8] = splat2(q2.x); s[9] = splat2(q2.y);
            #pragma unroll
            for (int kw = 0; kw < 3; kw++) {
                const ull* wp = (const ull*)&sW2[rr][kh * 3 + kw][nt * 8];
                ull w0 = wp[0], w1 = wp[1], w2 = wp[2], w3 = wp[3];
                #pragma unroll
                for (int p = 0; p < 8; p++) {
                    ffma2(acc2[p][0], s[kw + p], w0);
                    ffma2(acc2[p][1], s[kw + p], w1);
                    ffma2(acc2[p][2], s[kw + p], w2);
                    ffma2(acc2[p][3], s[kw + p], w3);
                }
            }
        }
    }
    int y = rowbase + row;
    #pragma unroll
    for (int k = 0; k < 4; k++) {
        int o = nt * 8 + 2 * k;
        float* op0 = out + ((size_t)(b * 64 + o) * 128 + y) * 128 + cb;
        float* op1 = op0 + 128 * 128;
        #pragma unroll
        for (int p = 0; p < 8; p++) {
            float2 v = unpk(acc2[p][k]);
            op0[p] += v.x;
            op1[p] += v.y;
        }
    }
}

// ---------------------------------------------------------------------------
extern "C" void kernel_launch(void* const* d_in, const int* in_sizes, int n_in,
                              void* d_out, int out_size) {
    const float* x1    = (const float*)d_in[0];
    const float* x2    = (const float*)d_in[1];
    const float* d1_w1 = (const float*)d_in[2];
    const float* d1_w2 = (const float*)d_in[3];
    const float* d2_w1 = (const float*)d_in[4];
    const float* d2_w2 = (const float*)d_in[5];
    const float* align_w = (const float*)d_in[6];
    const float* up_w1 = (const float*)d_in[7];
    const float* up_w2 = (const float*)d_in[8];
    const float* re_w1 = (const float*)d_in[9];
    const float* re_w2 = (const float*)d_in[10];
    float* out = (float*)d_out;

    weff_kernel<<<512, 64>>>(up_w1, up_w2);

    pool_kernel<<<4096, 256>>>(x1, x2);
    mlp_kernel<<<32, 128>>>(d1_w1, d1_w2);
    dsc_kernel<<<4096, 256>>>(x1, x2, 0);      // also produces pooled(t)
    mlp_kernel<<<32, 128>>>(d2_w1, d2_w2);
    dsc_kernel<<<4096, 256>>>(x1, x2, 1);

    align_kernel<<<dim3(4, 8, 16), 256>>>(align_w);
    upconv_kernel<<<dim3(16, 4, 16), 256>>>(out);

    reconv1_kernel<<<dim3(8, 16), 256>>>(out, re_w1);
    reconv2_kernel<<<dim3(64, 16), 256>>>(re_w2, out);
}

// round 3
// speedup vs baseline: 1.5424x; 1.1683x over previous
#include <cuda_runtime.h>
#include <math.h>

// ---------------------------------------------------------------------------
// DSFDecoder: B=16, C=128, H=W=64, OUT=64, CR=16, RE=8
// FFMA2 + cp.async double-buffered upconv + transposed weights.
// ---------------------------------------------------------------------------

#define PLANE 4096            // 64*64
#define CH    128
#define BATCH 16

typedef unsigned long long ull;

__device__ __forceinline__ void ffma2(ull& d, ull a, ull b) {
    asm("fma.rn.f32x2 %0, %1, %2, %0;" : "+l"(d) : "l"(a), "l"(b));
}
__device__ __forceinline__ ull splat2(float v) {
    ull r; asm("mov.b64 %0, {%1, %1};" : "=l"(r) : "f"(v)); return r;
}
__device__ __forceinline__ float2 unpk(ull v) {
    float2 f; asm("mov.b64 {%0, %1}, %2;" : "=f"(f.x), "=f"(f.y) : "l"(v)); return f;
}
__device__ __forceinline__ unsigned smaddr(const void* p) {
    return (unsigned)__cvta_generic_to_shared(p);
}
__device__ __forceinline__ void cp16(unsigned d, const void* s) {
    asm volatile("cp.async.cg.shared.global [%0], [%1], 16;" :: "r"(d), "l"(s) : "memory");
}
__device__ __forceinline__ void cp4z(unsigned d, const void* s, int valid) {
    asm volatile("cp.async.ca.shared.global [%0], [%1], 4, %2;"
                 :: "r"(d), "l"(s), "r"(valid ? 4 : 0) : "memory");
}
__device__ __forceinline__ void cp_commit() {
    asm volatile("cp.async.commit_group;" ::: "memory");
}
__device__ __forceinline__ void cp_wait1() {
    asm volatile("cp.async.wait_group 1;" ::: "memory");
}
__device__ __forceinline__ void cp_wait0() {
    asm volatile("cp.async.wait_group 0;" ::: "memory");
}

__device__ float g_t[2][BATCH * CH * PLANE];      // relu(dsc1)
__device__ float g_ab[2][BATCH * CH * PLANE];     // dsc2 outputs
__device__ float g_fused[BATCH * CH * PLANE];
__device__ float g_weffT[4 * 16 * 4608];          // [sub][cc16][c8][t9][o64]
__device__ float g_tre[BATCH * 8 * 128 * 128];
__device__ float g_pool[2][BATCH * CH];
__device__ float g_wk[2][BATCH * CH * 9];

// ---------------- pool + mlp1 fused (both slots): x -> pooled -> wk1 ------------
__global__ void poolmlp_kernel(const float* __restrict__ x1, const float* __restrict__ x2,
                               const float* __restrict__ w1, const float* __restrict__ w2) {
    int slot = blockIdx.x >> 4;
    int b = blockIdx.x & 15;
    int tid = threadIdx.x;
    int wid = tid >> 5, lane = tid & 31;
    const float* xb = (slot ? x2 : x1) + (size_t)b * CH * PLANE;
    __shared__ float sp[128], sh[16];
    // each warp: 16 channels
    for (int k = 0; k < 16; k++) {
        int c = wid * 16 + k;
        const float4* v = (const float4*)(xb + (size_t)c * PLANE);
        float s = 0.f;
        #pragma unroll 4
        for (int i = lane; i < 1024; i += 32) {
            float4 q = v[i];
            s += q.x + q.y + q.z + q.w;
        }
        for (int off = 16; off; off >>= 1) s += __shfl_xor_sync(0xffffffffu, s, off);
        if (lane == 0) sp[c] = s * (1.f / 4096.f);
    }
    __syncthreads();
    if (tid < 16) {
        float acc = 0.f;
        #pragma unroll 8
        for (int c = 0; c < 128; c++) acc += sp[c] * w1[tid * 128 + c];
        sh[tid] = 0.5f * acc * (1.f + erff(acc * 0.70710678118654752f));
    }
    __syncthreads();
    if (tid < 128) {
        int c = tid;
        float lg[9];
        float mx = -1e30f;
        #pragma unroll
        for (int k = 0; k < 9; k++) {
            float acc = 0.f;
            #pragma unroll
            for (int r = 0; r < 16; r++) acc += sh[r] * w2[(c * 9 + k) * 16 + r];
            lg[k] = acc;
            mx = fmaxf(mx, acc);
        }
        float ss = 0.f;
        #pragma unroll
        for (int k = 0; k < 9; k++) { lg[k] = expf(lg[k] - mx); ss += lg[k]; }
        float inv = 1.f / ss;
        #pragma unroll
        for (int k = 0; k < 9; k++) g_wk[slot][(b * 128 + c) * 9 + k] = lg[k] * inv;
    }
}

// ---------------- mlp2: g_pool -> wk2 ----------------
__global__ void mlp_kernel(const float* __restrict__ w1, const float* __restrict__ w2) {
    int slot = blockIdx.x >> 4;
    int b = blockIdx.x & 15;
    int tid = threadIdx.x;
    __shared__ float sp[128], sh[16];
    sp[tid] = g_pool[slot][b * 128 + tid];
    __syncthreads();
    if (tid < 16) {
        float acc = 0.f;
        #pragma unroll 8
        for (int c = 0; c < 128; c++) acc += sp[c] * w1[tid * 128 + c];
        sh[tid] = 0.5f * acc * (1.f + erff(acc * 0.70710678118654752f));
    }
    __syncthreads();
    int c = tid;
    float lg[9];
    float mx = -1e30f;
    #pragma unroll
    for (int k = 0; k < 9; k++) {
        float acc = 0.f;
        #pragma unroll
        for (int r = 0; r < 16; r++) acc += sh[r] * w2[(c * 9 + k) * 16 + r];
        lg[k] = acc;
        mx = fmaxf(mx, acc);
    }
    float ss = 0.f;
    #pragma unroll
    for (int k = 0; k < 9; k++) { lg[k] = expf(lg[k] - mx); ss += lg[k]; }
    float inv = 1.f / ss;
    #pragma unroll
    for (int k = 0; k < 9; k++) g_wk[slot][(b * 128 + c) * 9 + k] = lg[k] * inv;
}

// ---------------- dsc: depthwise 3x3 + residual, padded smem, no predicates ------
__global__ void __launch_bounds__(256, 2) dsc_kernel(const float* __restrict__ x1,
                                                     const float* __restrict__ x2,
                                                     int phase) {
    int slot = blockIdx.x >> 11;
    int bc = blockIdx.x & 2047;
    const float* xext = slot ? x2 : x1;
    const float* src = phase ? &g_t[slot][(size_t)bc * PLANE]
                             : xext + (size_t)bc * PLANE;
    float* dst = phase ? &g_ab[slot][(size_t)bc * PLANE]
                       : &g_t[slot][(size_t)bc * PLANE];
    float wk[9];
    #pragma unroll
    for (int k = 0; k < 9; k++) wk[k] = g_wk[slot][bc * 9 + k];
    __shared__ float sp[66][68];
    int tid = threadIdx.x;
    // zero borders: padded rows 0,65 cols 0..67; cols 0 and 65 of rows 1..64
    if (tid < 68) { sp[0][tid] = 0.f; sp[65][tid] = 0.f; }
    if (tid < 64) { sp[tid + 1][0] = 0.f; sp[tid + 1][65] = 0.f; }
    // interior fill: 16 consecutive px per thread
    {
        int p = tid * 16;
        int h = p >> 6, w = p & 63;
        const float4* s4 = (const float4*)(src + p);
        float4 q0 = s4[0], q1 = s4[1], q2 = s4[2], q3 = s4[3];
        float* d = &sp[h + 1][w + 1];
        d[0] = q0.x; d[1] = q0.y; d[2] = q0.z; d[3] = q0.w;
        d[4] = q1.x; d[5] = q1.y; d[6] = q1.z; d[7] = q1.w;
        d[8] = q2.x; d[9] = q2.y; d[10] = q2.z; d[11] = q2.w;
        d[12] = q3.x; d[13] = q3.y; d[14] = q3.z; d[15] = q3.w;
    }
    __syncthreads();
    int h = tid >> 2, xb = (tid & 3) * 16;
    float r0[20], r1[20], r2[20];
    #pragma unroll
    for (int k = 0; k < 5; k++) {
        *(float4*)&r0[k * 4] = *(const float4*)&sp[h + 0][xb + k * 4];
        *(float4*)&r1[k * 4] = *(const float4*)&sp[h + 1][xb + k * 4];
        *(float4*)&r2[k * 4] = *(const float4*)&sp[h + 2][xb + k * 4];
    }
    float acc[16];
    #pragma unroll
    for (int j = 0; j < 16; j++) {
        float a = r1[j + 1];   // residual
        a += wk[0] * r0[j];     a += wk[1] * r0[j + 1]; a += wk[2] * r0[j + 2];
        a += wk[3] * r1[j];     a += wk[4] * r1[j + 1]; a += wk[5] * r1[j + 2];
        a += wk[6] * r2[j];     a += wk[7] * r2[j + 1]; a += wk[8] * r2[j + 2];
        acc[j] = a;
    }
    int p = tid * 16;
    if (phase) {
        #pragma unroll
        for (int k = 0; k < 4; k++)
            *(float4*)&dst[p + k * 4] = make_float4(acc[k*4], acc[k*4+1], acc[k*4+2], acc[k*4+3]);
    } else {
        float psum = 0.f;
        #pragma unroll
        for (int j = 0; j < 16; j++) { acc[j] = fmaxf(acc[j], 0.f); psum += acc[j]; }
        #pragma unroll
        for (int k = 0; k < 4; k++)
            *(float4*)&dst[p + k * 4] = make_float4(acc[k*4], acc[k*4+1], acc[k*4+2], acc[k*4+3]);
        for (int off = 16; off; off >>= 1) psum += __shfl_xor_sync(0xffffffffu, psum, off);
        __shared__ float red[8];
        if ((tid & 31) == 0) red[tid >> 5] = psum;
        __syncthreads();
        if (tid < 32) {
            float r = (tid < 8) ? red[tid] : 0.f;
            for (int off = 4; off; off >>= 1) r += __shfl_xor_sync(0xffffffffu, r, off);
            if (tid == 0) g_pool[slot][bc] = r * (1.f / 4096.f);
        }
    }
}

// ---------------- align (blocks 512..1023) + weff (blocks 0..511) merged ----------
__global__ void __launch_bounds__(256, 2) alignweff_kernel(const float* __restrict__ aw,
                                                           const float* __restrict__ w1,
                                                           const float* __restrict__ w2) {
    __shared__ float smem_u[4096];
    int tid = threadIdx.x;
    if (blockIdx.x < 512) {
        // ---- weff: W_eff[sub][o][ci][t] = sum_c w2[o,c]*w1[4c+sub][ci][t], transposed out
        int sub = blockIdx.x >> 7, ci = blockIdx.x & 127;
        float* s1 = smem_u;   // [128*9]
        for (int i = tid; i < 1152; i += 256) {
            int c = i / 9, t = i - c * 9;
            s1[i] = w1[((size_t)(c * 4 + sub) * 128 + ci) * 9 + t];
        }
        __syncthreads();
        if (tid < 64) {
            int o = tid;
            float acc[9] = {0.f,0.f,0.f,0.f,0.f,0.f,0.f,0.f,0.f};
            for (int c = 0; c < 128; c++) {
                float wv = w2[o * 128 + c];
                #pragma unroll
                for (int t = 0; t < 9; t++) acc[t] += wv * s1[c * 9 + t];
            }
            int cc = ci >> 3, c8 = ci & 7;
            float* base = &g_weffT[(((size_t)sub * 16 + cc) * 8 + c8) * 576];
            #pragma unroll
            for (int t = 0; t < 9; t++) base[t * 64 + o] = acc[t];
        }
        return;
    }
    // ---- align
    int idx = blockIdx.x - 512;
    int q = idx & 3, og = (idx >> 2) & 7, b = idx >> 5;
    float (*sw_s)[16] = (float (*)[16])smem_u;   // [256][16]
    for (int i = tid; i < 4096; i += 256) {
        int c = i >> 4, oo = i & 15;
        sw_s[c][oo] = aw[(og * 16 + oo) * 256 + c];
    }
    __syncthreads();
    int pix = q * 1024 + tid * 4;
    const float* ap = &g_ab[0][(size_t)b * CH * PLANE] + pix;
    const float* bp = &g_ab[1][(size_t)b * CH * PLANE] + pix;
    ull acc2[8][4];
    #pragma unroll
    for (int jo = 0; jo < 8; jo++)
        #pragma unroll
        for (int p = 0; p < 4; p++) acc2[jo][p] = 0ull;
    for (int c = 0; c < 128; c++) {
        float4 xv = *(const float4*)(ap + (size_t)c * PLANE);
        ull s0 = splat2(xv.x), s1 = splat2(xv.y), s2 = splat2(xv.z), s3 = splat2(xv.w);
        const ull* wp = (const ull*)&sw_s[c][0];
        #pragma unroll
        for (int jo = 0; jo < 8; jo++) {
            ull wv = wp[jo];
            ffma2(acc2[jo][0], s0, wv);
            ffma2(acc2[jo][1], s1, wv);
            ffma2(acc2[jo][2], s2, wv);
            ffma2(acc2[jo][3], s3, wv);
        }
    }
    for (int c = 0; c < 128; c++) {
        float4 xv = *(const float4*)(bp + (size_t)c * PLANE);
        ull s0 = splat2(xv.x), s1 = splat2(xv.y), s2 = splat2(xv.z), s3 = splat2(xv.w);
        const ull* wp = (const ull*)&sw_s[128 + c][0];
        #pragma unroll
        for (int jo = 0; jo < 8; jo++) {
            ull wv = wp[jo];
            ffma2(acc2[jo][0], s0, wv);
            ffma2(acc2[jo][1], s1, wv);
            ffma2(acc2[jo][2], s2, wv);
            ffma2(acc2[jo][3], s3, wv);
        }
    }
    #pragma unroll
    for (int jo = 0; jo < 8; jo++) {
        int o = og * 16 + 2 * jo;
        float* f0 = &g_fused[((size_t)b * CH + o) * PLANE + pix];
        float* f1 = f0 + PLANE;
        #pragma unroll
        for (int p = 0; p < 4; p++) {
            float2 v = unpk(acc2[jo][p]);
            f0[p] = v.x;
            f1[p] = v.y;
        }
    }
}

// ---------------- main conv: cp.async double-buffered, FFMA2 -----------------------
// grid (16 rowgroups, 4 subs, 16 b); 256 thr; thread: 8 pixels x 8 outputs (4 o-pairs)
// dyn smem: 2 x (sIn 8*6*68 + sW 8*9*64) floats = 62976 B
#define UP_BUF 7872
__global__ void __launch_bounds__(256, 2) upconv_kernel(float* __restrict__ out) {
    extern __shared__ float dsm[];
    int b = blockIdx.z, sub = blockIdx.y, rg = blockIdx.x;
    int tid = threadIdx.x;
    int nt = tid & 7;
    int mt = tid >> 3;
    int row0 = rg * 4;
    int r = mt >> 3, cb = (mt & 7) * 8;

    const float* fb = g_fused + (size_t)b * CH * PLANE;
    const float* wT = g_weffT + (size_t)sub * 16 * 4608;

    // tile loader
    auto load_tile = [&](int ccidx, int buf) {
        float* sInb = dsm + buf * UP_BUF;
        float* sWb  = sInb + 3264;
        // weights: contiguous 16B chunks
        const float* wsrc = wT + ccidx * 4608;
        unsigned wdst = smaddr(sWb);
        for (int i = tid; i < 1152; i += 256)
            cp16(wdst + i * 16, wsrc + i * 4);
        // input: 4B chunks with zero-fill
        unsigned idst = smaddr(sInb);
        for (int i = tid; i < 3264; i += 256) {
            int c = i / 408, rem = i - c * 408;
            int rr = rem / 68, x = rem - rr * 68;
            int gr = row0 + rr - 1, gx = x - 1;
            int valid = ((unsigned)gr < 64u) & ((unsigned)gx < 64u);
            const float* src = fb + (size_t)(ccidx * 8 + c) * PLANE + (valid ? gr * 64 + gx : 0);
            cp4z(idst + i * 4, src, valid);
        }
    };

    ull acc2[8][4];
    #pragma unroll
    for (int p = 0; p < 8; p++)
        #pragma unroll
        for (int k = 0; k < 4; k++) acc2[p][k] = 0ull;

    load_tile(0, 0);
    cp_commit();

    for (int it = 0; it < 16; it++) {
        if (it < 15) {
            load_tile(it + 1, (it + 1) & 1);
            cp_commit();
            cp_wait1();
        } else {
            cp_wait0();
        }
        __syncthreads();
        const float* sIn = dsm + (it & 1) * UP_BUF;
        const float* sW  = sIn + 3264;
        for (int c = 0; c < 8; c++) {
            #pragma unroll
            for (int kh = 0; kh < 3; kh++) {
                const float4* ip4 = (const float4*)(sIn + c * 408 + (r + kh) * 68 + cb);
                float4 q0 = ip4[0], q1 = ip4[1], q2 = ip4[2];
                ull s[10];
                s[0] = splat2(q0.x); s[1] = splat2(q0.y); s[2] = splat2(q0.z); s[3] = splat2(q0.w);
                s[4] = splat2(q1.x); s[5] = splat2(q1.y); s[6] = splat2(q1.z); s[7] = splat2(q1.w);
                s[8] = splat2(q2.x); s[9] = splat2(q2.y);
                #pragma unroll
                for (int kw = 0; kw < 3; kw++) {
                    const ull* wp = (const ull*)(sW + c * 576 + (kh * 3 + kw) * 64 + nt * 8);
                    ull w0 = wp[0], w1 = wp[1], w2 = wp[2], w3 = wp[3];
                    #pragma unroll
                    for (int p = 0; p < 8; p++) {
                        ffma2(acc2[p][0], s[kw + p], w0);
                        ffma2(acc2[p][1], s[kw + p], w1);
                        ffma2(acc2[p][2], s[kw + p], w2);
                        ffma2(acc2[p][3], s[kw + p], w3);
                    }
                }
            }
        }
        __syncthreads();
    }
    int y = 2 * (row0 + r) + (sub >> 1);
    int r2 = sub & 1;
    #pragma unroll
    for (int k = 0; k < 4; k++) {
        int o = nt * 8 + 2 * k;
        float* op0 = out + ((size_t)(b * 64 + o) * 128 + y) * 128;
        float* op1 = op0 + 128 * 128;
        #pragma unroll
        for (int p = 0; p < 8; p++) {
            float2 v = unpk(acc2[p][k]);
            op0[2 * (cb + p) + r2] = v.x;
            op1[2 * (cb + p) + r2] = v.y;
        }
    }
}

// ---------------- refine conv1: tre = relu(conv3x3(up, re_w1)), FFMA2 ----------------
__global__ void __launch_bounds__(256, 2) reconv1_kernel(const float* __restrict__ up,
                                                         const float* __restrict__ w) {
    int b = blockIdx.y, rg = blockIdx.x;
    int tid = threadIdx.x;
    int row = tid >> 4;
    int cb = (tid & 15) * 8;
    int rowbase = rg * 16;
    __shared__ float sW1[64][9][8];
    __shared__ float sU[2][18][132];
    for (int i = tid; i < 64 * 9 * 8; i += 256) {
        int c = i / 72, rem = i - c * 72;
        int t = rem >> 3, rr = rem & 7;
        sW1[c][t][rr] = w[((size_t)rr * 64 + c) * 9 + t];
    }
    ull acc2[8][4];
    #pragma unroll
    for (int p = 0; p < 8; p++)
        #pragma unroll
        for (int k = 0; k < 4; k++) acc2[p][k] = 0ull;

    const float* ub = up + (size_t)b * 64 * 128 * 128;
    for (int cc = 0; cc < 64; cc += 2) {
        __syncthreads();
        for (int i = tid; i < 2 * 18 * 132; i += 256) {
            int c = i / 2376, rem = i - c * 2376;
            int rr = rem / 132, x = rem - rr * 132;
            int gy = rowbase + rr - 1, gx = x - 1;
            float v = 0.f;
            if ((unsigned)gy < 128u && (unsigned)gx < 128u)
                v = ub[(size_t)(cc + c) * 16384 + gy * 128 + gx];
            sU[c][rr][x] = v;
        }
        __syncthreads();
        #pragma unroll
        for (int c = 0; c < 2; c++) {
            #pragma unroll
            for (int kh = 0; kh < 3; kh++) {
                const float4* ip4 = (const float4*)&sU[c][row + kh][cb];
                float4 q0 = ip4[0], q1 = ip4[1], q2 = ip4[2];
                ull s[10];
                s[0] = splat2(q0.x); s[1] = splat2(q0.y); s[2] = splat2(q0.z); s[3] = splat2(q0.w);
                s[4] = splat2(q1.x); s[5] = splat2(q1.y); s[6] = splat2(q1.z); s[7] = splat2(q1.w);
                s[8] = splat2(q2.x); s[9] = splat2(q2.y);
                #pragma unroll
                for (int kw = 0; kw < 3; kw++) {
                    const ull* wp = (const ull*)&sW1[cc + c][kh * 3 + kw][0];
                    ull w0 = wp[0], w1 = wp[1], w2 = wp[2], w3 = wp[3];
                    #pragma unroll
                    for (int p = 0; p < 8; p++) {
                        ffma2(acc2[p][0], s[kw + p], w0);
                        ffma2(acc2[p][1], s[kw + p], w1);
                        ffma2(acc2[p][2], s[kw + p], w2);
                        ffma2(acc2[p][3], s[kw + p], w3);
                    }
                }
            }
        }
    }
    int y = rowbase + row;
    #pragma unroll
    for (int k = 0; k < 4; k++) {
        int rr = 2 * k;
        float* t0 = &g_tre[((size_t)(b * 8 + rr) * 128 + y) * 128 + cb];
        float* t1 = t0 + 128 * 128;
        #pragma unroll
        for (int p = 0; p < 8; p++) {
            float2 v = unpk(acc2[p][k]);
            t0[p] = fmaxf(v.x, 0.f);
            t1[p] = fmaxf(v.y, 0.f);
        }
    }
}

// ---------------- refine conv2 + residual: d_out += conv3x3(tre, re_w2), FFMA2 -------
__global__ void __launch_bounds__(256, 2) reconv2_kernel(const float* __restrict__ w,
                                                         float* __restrict__ out) {
    int b = blockIdx.y, rg = blockIdx.x;
    int tid = threadIdx.x;
    int nt = tid & 7;
    int mt = tid >> 3;
    int row = mt >> 4, cb = (mt & 15) * 8;
    int rowbase = rg * 2;
    __shared__ float sW2[8][9][64];
    __shared__ float sT[8][4][132];
    for (int i = tid; i < 8 * 9 * 64; i += 256) {
        int rr = i / 576, rem = i - rr * 576;
        int t = rem >> 6, o = rem & 63;
        sW2[rr][t][o] = w[((size_t)o * 8 + rr) * 9 + t];
    }
    for (int i = tid; i < 8 * 4 * 132; i += 256) {
        int c = i / 528, rem = i - c * 528;
        int rr = rem / 132, x = rem - rr * 132;
        int gy = rowbase + rr - 1, gx = x - 1;
        float v = 0.f;
        if ((unsigned)gy < 128u && (unsigned)gx < 128u)
            v = g_tre[((size_t)(b * 8 + c) * 128 + gy) * 128 + gx];
        sT[c][rr][x] = v;
    }
    __syncthreads();
    ull acc2[8][4];
    #pragma unroll
    for (int p = 0; p < 8; p++)
        #pragma unroll
        for (int k = 0; k < 4; k++) acc2[p][k] = 0ull;
    #pragma unroll
    for (int rr = 0; rr < 8; rr++) {
        #pragma unroll
        for (int kh = 0; kh < 3; kh++) {
            const float4* ip4 = (const float4*)&sT[rr][row + kh][cb];
            float4 q0 = ip4[0], q1 = ip4[1], q2 = ip4[2];
            ull s[10];
            s[0] = splat2(q0.x); s[1] = splat2(q0.y); s[2] = splat2(q0.z); s[3] = splat2(q0.w);
            s[4] = splat2(q1.x); s[5] = splat2(q1.y); s[6] = splat2(q1.z); s[7] = splat2(q1.w);
            s[8] = splat2(q2.x); s[9] = splat2(q2.y);
            #pragma unroll
            for (int kw = 0; kw < 3; kw++) {
                const ull* wp = (const ull*)&sW2[rr][kh * 3 + kw][nt * 8];
                ull w0 = wp[0], w1 = wp[1], w2 = wp[2], w3 = wp[3];
                #pragma unroll
                for (int p = 0; p < 8; p++) {
                    ffma2(acc2[p][0], s[kw + p], w0);
                    ffma2(acc2[p][1], s[kw + p], w1);
                    ffma2(acc2[p][2], s[kw + p], w2);
                    ffma2(acc2[p][3], s[kw + p], w3);
                }
            }
        }
    }
    int y = rowbase + row;
    #pragma unroll
    for (int k = 0; k < 4; k++) {
        int o = nt * 8 + 2 * k;
        float* op0 = out + ((size_t)(b * 64 + o) * 128 + y) * 128 + cb;
        float* op1 = op0 + 128 * 128;
        #pragma unroll
        for (int p = 0; p < 8; p++) {
            float2 v = unpk(acc2[p][k]);
            op0[p] += v.x;
            op1[p] += v.y;
        }
    }
}

// ---------------------------------------------------------------------------
extern "C" void kernel_launch(void* const* d_in, const int* in_sizes, int n_in,
                              void* d_out, int out_size) {
    const float* x1    = (const float*)d_in[0];
    const float* x2    = (const float*)d_in[1];
    const float* d1_w1 = (const float*)d_in[2];
    const float* d1_w2 = (const float*)d_in[3];
    const float* d2_w1 = (const float*)d_in[4];
    const float* d2_w2 = (const float*)d_in[5];
    const float* align_w = (const float*)d_in[6];
    const float* up_w1 = (const float*)d_in[7];
    const float* up_w2 = (const float*)d_in[8];
    const float* re_w1 = (const float*)d_in[9];
    const float* re_w2 = (const float*)d_in[10];
    float* out = (float*)d_out;

    static int smem_set = 0;
    if (!smem_set) {
        cudaFuncSetAttribute(upconv_kernel, cudaFuncAttributeMaxDynamicSharedMemorySize,
                             2 * UP_BUF * 4);
        smem_set = 1;
    }

    poolmlp_kernel<<<32, 256>>>(x1, x2, d1_w1, d1_w2);          // 0
    dsc_kernel<<<4096, 256>>>(x1, x2, 0);                       // 1 (also pools t)
    mlp_kernel<<<32, 128>>>(d2_w1, d2_w2);                      // 2
    dsc_kernel<<<4096, 256>>>(x1, x2, 1);                       // 3
    alignweff_kernel<<<1024, 256>>>(align_w, up_w1, up_w2);     // 4
    upconv_kernel<<<dim3(16, 4, 16), 256, 2 * UP_BUF * 4>>>(out); // 5  <- ncu target
    reconv1_kernel<<<dim3(8, 16), 256>>>(out, re_w1);           // 6
    reconv2_kernel<<<dim3(64, 16), 256>>>(re_w2, out);          // 7
}

// round 5
// speedup vs baseline: 1.9994x; 1.2963x over previous
#include <cuda_runtime.h>
#include <cuda_bf16.h>
#include <math.h>
#include <stdint.h>

// ---------------------------------------------------------------------------
// DSFDecoder: B=16, C=128, H=W=64, OUT=64, CR=16, RE=8
// Upconv via mma.sync bf16 (split hi/lo, 3 terms). Rest FFMA2.
// ---------------------------------------------------------------------------

#define PLANE 4096
#define CH    128
#define BATCH 16

typedef unsigned long long ull;

__device__ __forceinline__ void ffma2(ull& d, ull a, ull b) {
    asm("fma.rn.f32x2 %0, %1, %2, %0;" : "+l"(d) : "l"(a), "l"(b));
}
__device__ __forceinline__ ull splat2(float v) {
    ull r; asm("mov.b64 %0, {%1, %1};" : "=l"(r) : "f"(v)); return r;
}
__device__ __forceinline__ float2 unpk(ull v) {
    float2 f; asm("mov.b64 {%0, %1}, %2;" : "=f"(f.x), "=f"(f.y) : "l"(v)); return f;
}
__device__ __forceinline__ unsigned smaddr(const void* p) {
    return (unsigned)__cvta_generic_to_shared(p);
}
__device__ __forceinline__ void cp16(unsigned d, const void* s) {
    asm volatile("cp.async.cg.shared.global [%0], [%1], 16;" :: "r"(d), "l"(s) : "memory");
}
__device__ __forceinline__ void cp_commit() {
    asm volatile("cp.async.commit_group;" ::: "memory");
}
__device__ __forceinline__ void cp_wait0() {
    asm volatile("cp.async.wait_group 0;" ::: "memory");
}
__device__ __forceinline__ unsigned prmt(unsigned a, unsigned b, unsigned sel) {
    unsigned r; asm("prmt.b32 %0, %1, %2, %3;" : "=r"(r) : "r"(a), "r"(b), "r"(sel));
    return r;
}
__device__ __forceinline__ void ldsm4(unsigned* r, unsigned addr) {
    asm volatile("ldmatrix.sync.aligned.m8n8.x4.shared.b16 {%0,%1,%2,%3}, [%4];"
                 : "=r"(r[0]), "=r"(r[1]), "=r"(r[2]), "=r"(r[3]) : "r"(addr));
}
__device__ __forceinline__ void mma_bf16(float* d, const unsigned* a, unsigned b0, unsigned b1) {
    asm volatile(
        "mma.sync.aligned.m16n8k16.row.col.f32.bf16.bf16.f32 "
        "{%0,%1,%2,%3}, {%4,%5,%6,%7}, {%8,%9}, {%0,%1,%2,%3};"
        : "+f"(d[0]), "+f"(d[1]), "+f"(d[2]), "+f"(d[3])
        : "r"(a[0]), "r"(a[1]), "r"(a[2]), "r"(a[3]), "r"(b0), "r"(b1));
}

__device__ float g_t[2][BATCH * CH * PLANE];
__device__ float g_ab[2][BATCH * CH * PLANE];
__device__ unsigned g_fu[BATCH * PLANE * CH];            // [b][pix][c] packed (lo|hi<<16) bf16
__device__ __align__(16) unsigned char g_wpack[18 * 8 * 8192]; // [(tap*2+g)*8 + sub*2 + hl] 8KB tiles
__device__ float g_tre[BATCH * 8 * 128 * 128];
__device__ float g_pool[2][BATCH * CH];
__device__ float g_wk[2][BATCH * CH * 9];

// ---------------- pool + mlp1 fused ----------------
__global__ void poolmlp_kernel(const float* __restrict__ x1, const float* __restrict__ x2,
                               const float* __restrict__ w1, const float* __restrict__ w2) {
    int slot = blockIdx.x >> 4;
    int b = blockIdx.x & 15;
    int tid = threadIdx.x;
    int wid = tid >> 5, lane = tid & 31;
    const float* xb = (slot ? x2 : x1) + (size_t)b * CH * PLANE;
    __shared__ float sp[128], sh[16];
    for (int k = 0; k < 16; k++) {
        int c = wid * 16 + k;
        const float4* v = (const float4*)(xb + (size_t)c * PLANE);
        float s = 0.f;
        #pragma unroll 4
        for (int i = lane; i < 1024; i += 32) {
            float4 q = v[i];
            s += q.x + q.y + q.z + q.w;
        }
        for (int off = 16; off; off >>= 1) s += __shfl_xor_sync(0xffffffffu, s, off);
        if (lane == 0) sp[c] = s * (1.f / 4096.f);
    }
    __syncthreads();
    if (tid < 16) {
        float acc = 0.f;
        #pragma unroll 8
        for (int c = 0; c < 128; c++) acc += sp[c] * w1[tid * 128 + c];
        sh[tid] = 0.5f * acc * (1.f + erff(acc * 0.70710678118654752f));
    }
    __syncthreads();
    if (tid < 128) {
        int c = tid;
        float lg[9];
        float mx = -1e30f;
        #pragma unroll
        for (int k = 0; k < 9; k++) {
            float acc = 0.f;
            #pragma unroll
            for (int r = 0; r < 16; r++) acc += sh[r] * w2[(c * 9 + k) * 16 + r];
            lg[k] = acc;
            mx = fmaxf(mx, acc);
        }
        float ss = 0.f;
        #pragma unroll
        for (int k = 0; k < 9; k++) { lg[k] = expf(lg[k] - mx); ss += lg[k]; }
        float inv = 1.f / ss;
        #pragma unroll
        for (int k = 0; k < 9; k++) g_wk[slot][(b * 128 + c) * 9 + k] = lg[k] * inv;
    }
}

// ---------------- mlp2 ----------------
__global__ void mlp_kernel(const float* __restrict__ w1, const float* __restrict__ w2) {
    int slot = blockIdx.x >> 4;
    int b = blockIdx.x & 15;
    int tid = threadIdx.x;
    __shared__ float sp[128], sh[16];
    sp[tid] = g_pool[slot][b * 128 + tid];
    __syncthreads();
    if (tid < 16) {
        float acc = 0.f;
        #pragma unroll 8
        for (int c = 0; c < 128; c++) acc += sp[c] * w1[tid * 128 + c];
        sh[tid] = 0.5f * acc * (1.f + erff(acc * 0.70710678118654752f));
    }
    __syncthreads();
    int c = tid;
    float lg[9];
    float mx = -1e30f;
    #pragma unroll
    for (int k = 0; k < 9; k++) {
        float acc = 0.f;
        #pragma unroll
        for (int r = 0; r < 16; r++) acc += sh[r] * w2[(c * 9 + k) * 16 + r];
        lg[k] = acc;
        mx = fmaxf(mx, acc);
    }
    float ss = 0.f;
    #pragma unroll
    for (int k = 0; k < 9; k++) { lg[k] = expf(lg[k] - mx); ss += lg[k]; }
    float inv = 1.f / ss;
    #pragma unroll
    for (int k = 0; k < 9; k++) g_wk[slot][(b * 128 + c) * 9 + k] = lg[k] * inv;
}

// ---------------- dsc: depthwise 3x3 + residual ----------------
__global__ void __launch_bounds__(256, 3) dsc_kernel(const float* __restrict__ x1,
                                                     const float* __restrict__ x2,
                                                     int phase) {
    int slot = blockIdx.x >> 11;
    int bc = blockIdx.x & 2047;
    const float* xext = slot ? x2 : x1;
    const float* src = phase ? &g_t[slot][(size_t)bc * PLANE]
                             : xext + (size_t)bc * PLANE;
    float* dst = phase ? &g_ab[slot][(size_t)bc * PLANE]
                       : &g_t[slot][(size_t)bc * PLANE];
    float wk[9];
    #pragma unroll
    for (int k = 0; k < 9; k++) wk[k] = g_wk[slot][bc * 9 + k];
    __shared__ float sp[66][68];
    int tid = threadIdx.x;
    if (tid < 68) { sp[0][tid] = 0.f; sp[65][tid] = 0.f; }
    if (tid < 64) { sp[tid + 1][0] = 0.f; sp[tid + 1][65] = 0.f; }
    {
        int p = tid * 16;
        int h = p >> 6, w = p & 63;
        const float4* s4 = (const float4*)(src + p);
        float4 q0 = s4[0], q1 = s4[1], q2 = s4[2], q3 = s4[3];
        float* d = &sp[h + 1][w + 1];
        d[0] = q0.x; d[1] = q0.y; d[2] = q0.z; d[3] = q0.w;
        d[4] = q1.x; d[5] = q1.y; d[6] = q1.z; d[7] = q1.w;
        d[8] = q2.x; d[9] = q2.y; d[10] = q2.z; d[11] = q2.w;
        d[12] = q3.x; d[13] = q3.y; d[14] = q3.z; d[15] = q3.w;
    }
    __syncthreads();
    int h = tid >> 2, xb = (tid & 3) * 16;
    float r0[20], r1[20], r2[20];
    #pragma unroll
    for (int k = 0; k < 5; k++) {
        *(float4*)&r0[k * 4] = *(const float4*)&sp[h + 0][xb + k * 4];
        *(float4*)&r1[k * 4] = *(const float4*)&sp[h + 1][xb + k * 4];
        *(float4*)&r2[k * 4] = *(const float4*)&sp[h + 2][xb + k * 4];
    }
    float acc[16];
    #pragma unroll
    for (int j = 0; j < 16; j++) {
        float a = r1[j + 1];
        a += wk[0] * r0[j];     a += wk[1] * r0[j + 1]; a += wk[2] * r0[j + 2];
        a += wk[3] * r1[j];     a += wk[4] * r1[j + 1]; a += wk[5] * r1[j + 2];
        a += wk[6] * r2[j];     a += wk[7] * r2[j + 1]; a += wk[8] * r2[j + 2];
        acc[j] = a;
    }
    int p = tid * 16;
    if (phase) {
        #pragma unroll
        for (int k = 0; k < 4; k++)
            *(float4*)&dst[p + k * 4] = make_float4(acc[k*4], acc[k*4+1], acc[k*4+2], acc[k*4+3]);
    } else {
        float psum = 0.f;
        #pragma unroll
        for (int j = 0; j < 16; j++) { acc[j] = fmaxf(acc[j], 0.f); psum += acc[j]; }
        #pragma unroll
        for (int k = 0; k < 4; k++)
            *(float4*)&dst[p + k * 4] = make_float4(acc[k*4], acc[k*4+1], acc[k*4+2], acc[k*4+3]);
        for (int off = 16; off; off >>= 1) psum += __shfl_xor_sync(0xffffffffu, psum, off);
        __shared__ float red[8];
        if ((tid & 31) == 0) red[tid >> 5] = psum;
        __syncthreads();
        if (tid < 32) {
            float r = (tid < 8) ? red[tid] : 0.f;
            for (int off = 4; off; off >>= 1) r += __shfl_xor_sync(0xffffffffu, r, off);
            if (tid == 0) g_pool[slot][bc] = r * (1.f / 4096.f);
        }
    }
}

// ---------------- align (+weff-pack on first 512 blocks) ----------------
__global__ void __launch_bounds__(256, 2) alignweff_kernel(const float* __restrict__ aw,
                                                           const float* __restrict__ w1,
                                                           const float* __restrict__ w2) {
    __shared__ float smem_u[4096];
    int tid = threadIdx.x;
    if (blockIdx.x < 512) {
        // weff -> packed bf16 hi/lo tiles [o(64)][c(64)] SW128
        int sub = blockIdx.x >> 7, ci = blockIdx.x & 127;
        float* s1 = smem_u;
        for (int i = tid; i < 1152; i += 256) {
            int c = i / 9, t = i - c * 9;
            s1[i] = w1[((size_t)(c * 4 + sub) * 128 + ci) * 9 + t];
        }
        __syncthreads();
        if (tid < 64) {
            int o = tid;
            float acc[9] = {0.f,0.f,0.f,0.f,0.f,0.f,0.f,0.f,0.f};
            for (int c = 0; c < 128; c++) {
                float wv = w2[o * 128 + c];
                #pragma unroll
                for (int t = 0; t < 9; t++) acc[t] += wv * s1[c * 9 + t];
            }
            int g = ci >> 6, cl = ci & 63;
            unsigned off = ((o >> 3) << 10) + ((o & 7) << 7) + (cl << 1);
            unsigned sw = off ^ ((off >> 3) & 0x70);
            #pragma unroll
            for (int t = 0; t < 9; t++) {
                float v = acc[t];
                __nv_bfloat16 hb = __float2bfloat16(v);
                __nv_bfloat16 lb = __float2bfloat16(v - __bfloat162float(hb));
                unsigned char* base = g_wpack + ((size_t)((t * 2 + g) * 8 + sub * 2)) * 8192;
                *(__nv_bfloat16*)(base + sw) = hb;
                *(__nv_bfloat16*)(base + 8192 + sw) = lb;
            }
        }
        return;
    }
    // align: fused = concat(a,b) @ aw^T -> g_fu transposed + packed bf16 hi/lo
    int idx = blockIdx.x - 512;
    int q = idx & 3, og = (idx >> 2) & 7, b = idx >> 5;
    float (*sw_s)[16] = (float (*)[16])smem_u;
    for (int i = tid; i < 4096; i += 256) {
        int c = i >> 4, oo = i & 15;
        sw_s[c][oo] = aw[(og * 16 + oo) * 256 + c];
    }
    __syncthreads();
    int pix = q * 1024 + tid * 4;
    const float* ap = &g_ab[0][(size_t)b * CH * PLANE] + pix;
    const float* bp = &g_ab[1][(size_t)b * CH * PLANE] + pix;
    ull acc2[8][4];
    #pragma unroll
    for (int jo = 0; jo < 8; jo++)
        #pragma unroll
        for (int p = 0; p < 4; p++) acc2[jo][p] = 0ull;
    for (int c = 0; c < 128; c++) {
        float4 xv = *(const float4*)(ap + (size_t)c * PLANE);
        ull s0 = splat2(xv.x), s1 = splat2(xv.y), s2 = splat2(xv.z), s3 = splat2(xv.w);
        const ull* wp = (const ull*)&sw_s[c][0];
        #pragma unroll
        for (int jo = 0; jo < 8; jo++) {
            ull wv = wp[jo];
            ffma2(acc2[jo][0], s0, wv); ffma2(acc2[jo][1], s1, wv);
            ffma2(acc2[jo][2], s2, wv); ffma2(acc2[jo][3], s3, wv);
        }
    }
    for (int c = 0; c < 128; c++) {
        float4 xv = *(const float4*)(bp + (size_t)c * PLANE);
        ull s0 = splat2(xv.x), s1 = splat2(xv.y), s2 = splat2(xv.z), s3 = splat2(xv.w);
        const ull* wp = (const ull*)&sw_s[128 + c][0];
        #pragma unroll
        for (int jo = 0; jo < 8; jo++) {
            ull wv = wp[jo];
            ffma2(acc2[jo][0], s0, wv); ffma2(acc2[jo][1], s1, wv);
            ffma2(acc2[jo][2], s2, wv); ffma2(acc2[jo][3], s3, wv);
        }
    }
    unsigned* fb = g_fu + (size_t)b * PLANE * CH;
    #pragma unroll
    for (int p = 0; p < 4; p++) {
        unsigned wbuf[16];
        #pragma unroll
        for (int jo = 0; jo < 8; jo++) {
            float2 v = unpk(acc2[jo][p]);
            __nv_bfloat16 h0 = __float2bfloat16(v.x);
            __nv_bfloat16 l0 = __float2bfloat16(v.x - __bfloat162float(h0));
            __nv_bfloat16 h1 = __float2bfloat16(v.y);
            __nv_bfloat16 l1 = __float2bfloat16(v.y - __bfloat162float(h1));
            wbuf[2*jo]   = (unsigned)__bfloat16_as_ushort(l0) | ((unsigned)__bfloat16_as_ushort(h0) << 16);
            wbuf[2*jo+1] = (unsigned)__bfloat16_as_ushort(l1) | ((unsigned)__bfloat16_as_ushort(h1) << 16);
        }
        unsigned* dstw = fb + (size_t)(pix + p) * CH + og * 16;
        #pragma unroll
        for (int k = 0; k < 4; k++)
            *(uint4*)(dstw + k * 4) = *(uint4*)(wbuf + k * 4);
    }
}

// ---------------- upconv via mma.sync bf16 split --------------------------------
// grid 512 = 16 b x 32 rowpairs; 256 thr (8 warps); per block M=128 px, N=64, 4 subs
// buffer: A_hi 16KB | A_lo 16KB | B 64KB  (x2 double-buffered) = 192KB + align
#define UPC_BUF 98304
#define UPC_SMEM (2 * UPC_BUF + 1024)
__global__ void __launch_bounds__(256, 1) upconv_mma(float* __restrict__ out) {
    extern __shared__ char dynraw[];
    char* base = (char*)((((uintptr_t)dynraw) + 1023) & ~(uintptr_t)1023);
    int tid = threadIdx.x;
    int w = tid >> 5, lane = tid & 31;
    int b = blockIdx.x >> 5;
    int y0 = (blockIdx.x & 31) * 2;

    const unsigned* fb = g_fu + (size_t)b * PLANE * CH;
    int m = tid >> 1, half = tid & 1;
    int mrow = m >> 6, mx = m & 63;

    float acc[4][8][4];
    #pragma unroll
    for (int s = 0; s < 4; s++)
        #pragma unroll
        for (int nf = 0; nf < 8; nf++)
            #pragma unroll
            for (int r = 0; r < 4; r++) acc[s][nf][r] = 0.f;

    // fill chunk q into buffer buf
    auto fill = [&](int q, int buf) {
        char* bb = base + buf * UPC_BUF;
        int tap = q >> 1, g = q & 1;
        int kh = tap / 3, kw = tap - kh * 3;
        // B: 64KB via cp.async
        {
            const unsigned char* bsrc = g_wpack + (size_t)q * 65536;
            unsigned bdst = smaddr(bb + 32768);
            #pragma unroll 4
            for (int i = tid; i < 4096; i += 256)
                cp16(bdst + i * 16, bsrc + i * 16);
        }
        // A: 128 px x 64 ch -> hi/lo bf16, SW128 rows of 128B
        {
            int yy = y0 + mrow + kh - 1;
            int xx = mx + kw - 1;
            bool valid = ((unsigned)yy < 64u) && ((unsigned)xx < 64u);
            const uint4* s4 = (const uint4*)(fb + ((size_t)(yy * 64 + xx) * CH + g * 64 + half * 32));
            char* aHi = bb;
            char* aLo = bb + 16384;
            unsigned db = (unsigned)(m * 128 + half * 64);
            #pragma unroll
            for (int j = 0; j < 4; j++) {
                uint4 w0 = make_uint4(0u,0u,0u,0u), w1 = make_uint4(0u,0u,0u,0u);
                if (valid) { w0 = s4[2 * j]; w1 = s4[2 * j + 1]; }
                uint4 hi, lo;
                hi.x = prmt(w0.x, w0.y, 0x7632); hi.y = prmt(w0.z, w0.w, 0x7632);
                hi.z = prmt(w1.x, w1.y, 0x7632); hi.w = prmt(w1.z, w1.w, 0x7632);
                lo.x = prmt(w0.x, w0.y, 0x5410); lo.y = prmt(w0.z, w0.w, 0x5410);
                lo.z = prmt(w1.x, w1.y, 0x5410); lo.w = prmt(w1.z, w1.w, 0x5410);
                unsigned off = db + j * 16;
                unsigned sw = off ^ ((off >> 3) & 0x70);
                *(uint4*)(aHi + sw) = hi;
                *(uint4*)(aLo + sw) = lo;
            }
        }
    };

    fill(0, 0);
    cp_commit(); cp_wait0();
    __syncthreads();

    for (int q = 0; q < 18; q++) {
        int buf = q & 1;
        if (q < 17) { fill(q + 1, buf ^ 1); cp_commit(); }
        // compute chunk q from buf
        char* bb = base + buf * UPC_BUF;
        unsigned aHiB = smaddr(bb), aLoB = smaddr(bb + 16384);
        unsigned bB = smaddr(bb + 32768);
        #pragma unroll
        for (int kf = 0; kf < 4; kf++) {
            unsigned aH[4], aL[4];
            {
                unsigned arow = (unsigned)(16 * w + (lane & 15));
                unsigned aoff = arow * 128 + kf * 32 + ((lane >> 4) << 4);
                unsigned asw = aoff ^ ((aoff >> 3) & 0x70);
                ldsm4(aH, aHiB + asw);
                ldsm4(aL, aLoB + asw);
            }
            #pragma unroll
            for (int s = 0; s < 4; s++) {
                #pragma unroll
                for (int n0g = 0; n0g < 4; n0g++) {
                    unsigned brow = (unsigned)(16 * n0g + (lane & 15));
                    unsigned boff = brow * 128 + kf * 32 + ((lane >> 4) << 4);
                    unsigned bsw = boff ^ ((boff >> 3) & 0x70);
                    unsigned bH[4], bL[4];
                    ldsm4(bH, bB + s * 16384 + bsw);
                    ldsm4(bL, bB + s * 16384 + 8192 + bsw);
                    float* dA = acc[s][2 * n0g];
                    float* dB = acc[s][2 * n0g + 1];
                    mma_bf16(dA, aH, bH[0], bH[2]);
                    mma_bf16(dB, aH, bH[1], bH[3]);
                    mma_bf16(dA, aH, bL[0], bL[2]);
                    mma_bf16(dB, aH, bL[1], bL[3]);
                    mma_bf16(dA, aL, bH[0], bH[2]);
                    mma_bf16(dB, aL, bH[1], bH[3]);
                }
            }
        }
        if (q < 17) cp_wait0();
        __syncthreads();
    }

    // epilogue: pair subs (2sp, 2sp+1) -> float2 (even/odd x), via padded smem
    float2* s2 = (float2*)base;   // [128][65] float2 = 66.6KB
    int m0 = 16 * w + (lane >> 2);
    int ocol = (lane & 3) * 2;
    #pragma unroll
    for (int sp = 0; sp < 2; sp++) {
        __syncthreads();
        #pragma unroll
        for (int nf = 0; nf < 8; nf++) {
            int o = nf * 8 + ocol;
            s2[m0 * 65 + o]         = make_float2(acc[2*sp][nf][0], acc[2*sp+1][nf][0]);
            s2[m0 * 65 + o + 1]     = make_float2(acc[2*sp][nf][1], acc[2*sp+1][nf][1]);
            s2[(m0 + 8) * 65 + o]   = make_float2(acc[2*sp][nf][2], acc[2*sp+1][nf][2]);
            s2[(m0 + 8) * 65 + o+1] = make_float2(acc[2*sp][nf][3], acc[2*sp+1][nf][3]);
        }
        __syncthreads();
        for (int i = tid; i < 8192; i += 256) {
            int mr = i >> 12, o = (i >> 6) & 63, xx = i & 63;
            int y = 2 * (y0 + mr) + sp;
            *(float2*)(out + (((size_t)(b * 64 + o) * 128 + y) * 128 + 2 * xx)) =
                s2[(mr * 64 + xx) * 65 + o];
        }
    }
}

// ---------------- refine conv1: tre = relu(conv3x3(up, re_w1)), FFMA2 ----------------
__global__ void __launch_bounds__(256, 2) reconv1_kernel(const float* __restrict__ up,
                                                         const float* __restrict__ w) {
    int b = blockIdx.y, rg = blockIdx.x;
    int tid = threadIdx.x;
    int row = tid >> 4;
    int cb = (tid & 15) * 8;
    int rowbase = rg * 16;
    __shared__ float sW1[64][9][8];
    __shared__ float sU[2][18][132];
    for (int i = tid; i < 64 * 9 * 8; i += 256) {
        int c = i / 72, rem = i - c * 72;
        int t = rem >> 3, rr = rem & 7;
        sW1[c][t][rr] = w[((size_t)rr * 64 + c) * 9 + t];
    }
    ull acc2[8][4];
    #pragma unroll
    for (int p = 0; p < 8; p++)
        #pragma unroll
        for (int k = 0; k < 4; k++) acc2[p][k] = 0ull;

    const float* ub = up + (size_t)b * 64 * 128 * 128;
    for (int cc = 0; cc < 64; cc += 2) {
        __syncthreads();
        for (int i = tid; i < 2 * 18 * 132; i += 256) {
            int c = i / 2376, rem = i - c * 2376;
            int rr = rem / 132, x = rem - rr * 132;
            int gy = rowbase + rr - 1, gx = x - 1;
            float v = 0.f;
            if ((unsigned)gy < 128u && (unsigned)gx < 128u)
                v = ub[(size_t)(cc + c) * 16384 + gy * 128 + gx];
            sU[c][rr][x] = v;
        }
        __syncthreads();
        #pragma unroll
        for (int c = 0; c < 2; c++) {
            #pragma unroll
            for (int kh = 0; kh < 3; kh++) {
                const float4* ip4 = (const float4*)&sU[c][row + kh][cb];
                float4 q0 = ip4[0], q1 = ip4[1], q2 = ip4[2];
                ull s[10];
                s[0] = splat2(q0.x); s[1] = splat2(q0.y); s[2] = splat2(q0.z); s[3] = splat2(q0.w);
                s[4] = splat2(q1.x); s[5] = splat2(q1.y); s[6] = splat2(q1.z); s[7] = splat2(q1.w);
                s[8] = splat2(q2.x); s[9] = splat2(q2.y);
                #pragma unroll
                for (int kw = 0; kw < 3; kw++) {
                    const ull* wp = (const ull*)&sW1[cc + c][kh * 3 + kw][0];
                    ull w0 = wp[0], w1 = wp[1], w2 = wp[2], w3 = wp[3];
                    #pragma unroll
                    for (int p = 0; p < 8; p++) {
                        ffma2(acc2[p][0], s[kw + p], w0);
                        ffma2(acc2[p][1], s[kw + p], w1);
                        ffma2(acc2[p][2], s[kw + p], w2);
                        ffma2(acc2[p][3], s[kw + p], w3);
                    }
                }
            }
        }
    }
    int y = rowbase + row;
    #pragma unroll
    for (int k = 0; k < 4; k++) {
        int rr = 2 * k;
        float* t0 = &g_tre[((size_t)(b * 8 + rr) * 128 + y) * 128 + cb];
        float* t1 = t0 + 128 * 128;
        #pragma unroll
        for (int p = 0; p < 8; p++) {
            float2 v = unpk(acc2[p][k]);
            t0[p] = fmaxf(v.x, 0.f);
            t1[p] = fmaxf(v.y, 0.f);
        }
    }
}

// ---------------- refine conv2 + residual ----------------
__global__ void __launch_bounds__(256, 2) reconv2_kernel(const float* __restrict__ w,
                                                         float* __restrict__ out) {
    int b = blockIdx.y, rg = blockIdx.x;
    int tid = threadIdx.x;
    int nt = tid & 7;
    int mt = tid >> 3;
    int row = mt >> 4, cb = (mt & 15) * 8;
    int rowbase = rg * 2;
    __shared__ float sW2[8][9][64];
    __shared__ float sT[8][4][132];
    for (int i = tid; i < 8 * 9 * 64; i += 256) {
        int rr = i / 576, rem = i - rr * 576;
        int t = rem >> 6, o = rem & 63;
        sW2[rr][t][o] = w[((size_t)o * 8 + rr) * 9 + t];
    }
    for (int i = tid; i < 8 * 4 * 132; i += 256) {
        int c = i / 528, rem = i - c * 528;
        int rr = rem / 132, x = rem - rr * 132;
        int gy = rowbase + rr - 1, gx = x - 1;
        float v = 0.f;
        if ((unsigned)gy < 128u && (unsigned)gx < 128u)
            v = g_tre[((size_t)(b * 8 + c) * 128 + gy) * 128 + gx];
        sT[c][rr][x] = v;
    }
    __syncthreads();
    ull acc2[8][4];
    #pragma unroll
    for (int p = 0; p < 8; p++)
        #pragma unroll
        for (int k = 0; k < 4; k++) acc2[p][k] = 0ull;
    #pragma unroll
    for (int rr = 0; rr < 8; rr++) {
        #pragma unroll
        for (int kh = 0; kh < 3; kh++) {
            const float4* ip4 = (const float4*)&sT[rr][row + kh][cb];
            float4 q0 = ip4[0], q1 = ip4[1], q2 = ip4[2];
            ull s[10];
            s[0] = splat2(q0.x); s[1] = splat2(q0.y); s[2] = splat2(q0.z); s[3] = splat2(q0.w);
            s[4] = splat2(q1.x); s[5] = splat2(q1.y); s[6] = splat2(q1.z); s[7] = splat2(q1.w);
            s[8] = splat2(q2.x); s[9] = splat2(q2.y);
            #pragma unroll
            for (int kw = 0; kw < 3; kw++) {
                const ull* wp = (const ull*)&sW2[rr][kh * 3 + kw][nt * 8];
                ull w0 = wp[0], w1 = wp[1], w2 = wp[2], w3 = wp[3];
                #pragma unroll
                for (int p = 0; p < 8; p++) {
                    ffma2(acc2[p][0], s[kw + p], w0);
                    ffma2(acc2[p][1], s[kw + p], w1);
                    ffma2(acc2[p][2], s[kw + p], w2);
                    ffma2(acc2[p][3], s[kw + p], w3);
                }
            }
        }
    }
    int y = rowbase + row;
    #pragma unroll
    for (int k = 0; k < 4; k++) {
        int o = nt * 8 + 2 * k;
        float* op0 = out + ((size_t)(b * 64 + o) * 128 + y) * 128 + cb;
        float* op1 = op0 + 128 * 128;
        #pragma unroll
        for (int p = 0; p < 8; p++) {
            float2 v = unpk(acc2[p][k]);
            op0[p] += v.x;
            op1[p] += v.y;
        }
    }
}

// ---------------------------------------------------------------------------
extern "C" void kernel_launch(void* const* d_in, const int* in_sizes, int n_in,
                              void* d_out, int out_size) {
    const float* x1    = (const float*)d_in[0];
    const float* x2    = (const float*)d_in[1];
    const float* d1_w1 = (const float*)d_in[2];
    const float* d1_w2 = (const float*)d_in[3];
    const float* d2_w1 = (const float*)d_in[4];
    const float* d2_w2 = (const float*)d_in[5];
    const float* align_w = (const float*)d_in[6];
    const float* up_w1 = (const float*)d_in[7];
    const float* up_w2 = (const float*)d_in[8];
    const float* re_w1 = (const float*)d_in[9];
    const float* re_w2 = (const float*)d_in[10];
    float* out = (float*)d_out;

    static int smem_set = 0;
    if (!smem_set) {
        cudaFuncSetAttribute(upconv_mma, cudaFuncAttributeMaxDynamicSharedMemorySize, UPC_SMEM);
        smem_set = 1;
    }

    poolmlp_kernel<<<32, 256>>>(x1, x2, d1_w1, d1_w2);
    dsc_kernel<<<4096, 256>>>(x1, x2, 0);
    mlp_kernel<<<32, 128>>>(d2_w1, d2_w2);
    dsc_kernel<<<4096, 256>>>(x1, x2, 1);
    alignweff_kernel<<<1024, 256>>>(align_w, up_w1, up_w2);
    upconv_mma<<<512, 256, UPC_SMEM>>>(out);
    reconv1_kernel<<<dim3(8, 16), 256>>>(out, re_w1);
    reconv2_kernel<<<dim3(64, 16), 256>>>(re_w2, out);
}

// round 6
// speedup vs baseline: 2.0161x; 1.0084x over previous
#include <cuda_runtime.h>
#include <cuda_bf16.h>
#include <math.h>
#include <stdint.h>

// ---------------------------------------------------------------------------
// DSFDecoder: B=16, C=128, H=W=64, OUT=64, CR=16, RE=8
// Upconv + refine convs via mma.sync bf16 (split hi/lo, 3 terms). Rest FFMA2.
// ---------------------------------------------------------------------------

#define PLANE 4096
#define CH    128
#define BATCH 16

typedef unsigned long long ull;

__device__ __forceinline__ void ffma2(ull& d, ull a, ull b) {
    asm("fma.rn.f32x2 %0, %1, %2, %0;" : "+l"(d) : "l"(a), "l"(b));
}
__device__ __forceinline__ ull splat2(float v) {
    ull r; asm("mov.b64 %0, {%1, %1};" : "=l"(r) : "f"(v)); return r;
}
__device__ __forceinline__ float2 unpk(ull v) {
    float2 f; asm("mov.b64 {%0, %1}, %2;" : "=f"(f.x), "=f"(f.y) : "l"(v)); return f;
}
__device__ __forceinline__ unsigned smaddr(const void* p) {
    return (unsigned)__cvta_generic_to_shared(p);
}
__device__ __forceinline__ void cp16(unsigned d, const void* s) {
    asm volatile("cp.async.cg.shared.global [%0], [%1], 16;" :: "r"(d), "l"(s) : "memory");
}
__device__ __forceinline__ void cp_commit() {
    asm volatile("cp.async.commit_group;" ::: "memory");
}
__device__ __forceinline__ void cp_wait0() {
    asm volatile("cp.async.wait_group 0;" ::: "memory");
}
__device__ __forceinline__ unsigned prmt(unsigned a, unsigned b, unsigned sel) {
    unsigned r; asm("prmt.b32 %0, %1, %2, %3;" : "=r"(r) : "r"(a), "r"(b), "r"(sel));
    return r;
}
__device__ __forceinline__ void ldsm4(unsigned* r, unsigned addr) {
    asm volatile("ldmatrix.sync.aligned.m8n8.x4.shared.b16 {%0,%1,%2,%3}, [%4];"
                 : "=r"(r[0]), "=r"(r[1]), "=r"(r[2]), "=r"(r[3]) : "r"(addr));
}
__device__ __forceinline__ void mma_bf16(float* d, const unsigned* a, unsigned b0, unsigned b1) {
    asm volatile(
        "mma.sync.aligned.m16n8k16.row.col.f32.bf16.bf16.f32 "
        "{%0,%1,%2,%3}, {%4,%5,%6,%7}, {%8,%9}, {%0,%1,%2,%3};"
        : "+f"(d[0]), "+f"(d[1]), "+f"(d[2]), "+f"(d[3])
        : "r"(a[0]), "r"(a[1]), "r"(a[2]), "r"(a[3]), "r"(b0), "r"(b1));
}
__device__ __forceinline__ unsigned packbf(float v) {
    __nv_bfloat16 h = __float2bfloat16(v);
    __nv_bfloat16 l = __float2bfloat16(v - __bfloat162float(h));
    return (unsigned)__bfloat16_as_ushort(l) | ((unsigned)__bfloat16_as_ushort(h) << 16);
}

__device__ float g_t[2][BATCH * CH * PLANE];
__device__ float g_ab[2][BATCH * CH * PLANE];
__device__ unsigned g_fu[BATCH * PLANE * CH];            // [b][pix][c] packed (lo|hi<<16) bf16
__device__ __align__(16) unsigned char g_wpack[18 * 8 * 8192]; // upconv weights
__device__ unsigned g_upb[BATCH * 16384 * 64];           // [b][y][x][o] packed up
__device__ unsigned g_treb[BATCH * 16384 * 8];           // [b][y][x][r] packed tre
__device__ __align__(16) unsigned char g_w1pack[9 * 4096];   // [tap][16rows x 128B sw] hi|+2048 lo
__device__ __align__(16) unsigned char g_w2pack[2 * 11264];  // [64 rows x 176B] hi | lo
__device__ float g_pool[2][BATCH * CH];
__device__ float g_wk[2][BATCH * CH * 9];

// ---------------- pool + mlp1 fused ----------------
__global__ void poolmlp_kernel(const float* __restrict__ x1, const float* __restrict__ x2,
                               const float* __restrict__ w1, const float* __restrict__ w2) {
    int slot = blockIdx.x >> 4;
    int b = blockIdx.x & 15;
    int tid = threadIdx.x;
    int wid = tid >> 5, lane = tid & 31;
    const float* xb = (slot ? x2 : x1) + (size_t)b * CH * PLANE;
    __shared__ float sp[128], sh[16];
    for (int k = 0; k < 16; k++) {
        int c = wid * 16 + k;
        const float4* v = (const float4*)(xb + (size_t)c * PLANE);
        float s = 0.f;
        #pragma unroll 4
        for (int i = lane; i < 1024; i += 32) {
            float4 q = v[i];
            s += q.x + q.y + q.z + q.w;
        }
        for (int off = 16; off; off >>= 1) s += __shfl_xor_sync(0xffffffffu, s, off);
        if (lane == 0) sp[c] = s * (1.f / 4096.f);
    }
    __syncthreads();
    if (tid < 16) {
        float acc = 0.f;
        #pragma unroll 8
        for (int c = 0; c < 128; c++) acc += sp[c] * w1[tid * 128 + c];
        sh[tid] = 0.5f * acc * (1.f + erff(acc * 0.70710678118654752f));
    }
    __syncthreads();
    if (tid < 128) {
        int c = tid;
        float lg[9];
        float mx = -1e30f;
        #pragma unroll
        for (int k = 0; k < 9; k++) {
            float acc = 0.f;
            #pragma unroll
            for (int r = 0; r < 16; r++) acc += sh[r] * w2[(c * 9 + k) * 16 + r];
            lg[k] = acc;
            mx = fmaxf(mx, acc);
        }
        float ss = 0.f;
        #pragma unroll
        for (int k = 0; k < 9; k++) { lg[k] = expf(lg[k] - mx); ss += lg[k]; }
        float inv = 1.f / ss;
        #pragma unroll
        for (int k = 0; k < 9; k++) g_wk[slot][(b * 128 + c) * 9 + k] = lg[k] * inv;
    }
}

// ---------------- mlp2 ----------------
__global__ void mlp_kernel(const float* __restrict__ w1, const float* __restrict__ w2) {
    int slot = blockIdx.x >> 4;
    int b = blockIdx.x & 15;
    int tid = threadIdx.x;
    __shared__ float sp[128], sh[16];
    sp[tid] = g_pool[slot][b * 128 + tid];
    __syncthreads();
    if (tid < 16) {
        float acc = 0.f;
        #pragma unroll 8
        for (int c = 0; c < 128; c++) acc += sp[c] * w1[tid * 128 + c];
        sh[tid] = 0.5f * acc * (1.f + erff(acc * 0.70710678118654752f));
    }
    __syncthreads();
    int c = tid;
    float lg[9];
    float mx = -1e30f;
    #pragma unroll
    for (int k = 0; k < 9; k++) {
        float acc = 0.f;
        #pragma unroll
        for (int r = 0; r < 16; r++) acc += sh[r] * w2[(c * 9 + k) * 16 + r];
        lg[k] = acc;
        mx = fmaxf(mx, acc);
    }
    float ss = 0.f;
    #pragma unroll
    for (int k = 0; k < 9; k++) { lg[k] = expf(lg[k] - mx); ss += lg[k]; }
    float inv = 1.f / ss;
    #pragma unroll
    for (int k = 0; k < 9; k++) g_wk[slot][(b * 128 + c) * 9 + k] = lg[k] * inv;
}

// ---------------- dsc: depthwise 3x3 + residual ----------------
__global__ void __launch_bounds__(256, 3) dsc_kernel(const float* __restrict__ x1,
                                                     const float* __restrict__ x2,
                                                     int phase) {
    int slot = blockIdx.x >> 11;
    int bc = blockIdx.x & 2047;
    const float* xext = slot ? x2 : x1;
    const float* src = phase ? &g_t[slot][(size_t)bc * PLANE]
                             : xext + (size_t)bc * PLANE;
    float* dst = phase ? &g_ab[slot][(size_t)bc * PLANE]
                       : &g_t[slot][(size_t)bc * PLANE];
    float wk[9];
    #pragma unroll
    for (int k = 0; k < 9; k++) wk[k] = g_wk[slot][bc * 9 + k];
    __shared__ float sp[66][68];
    int tid = threadIdx.x;
    if (tid < 68) { sp[0][tid] = 0.f; sp[65][tid] = 0.f; }
    if (tid < 64) { sp[tid + 1][0] = 0.f; sp[tid + 1][65] = 0.f; }
    {
        int p = tid * 16;
        int h = p >> 6, w = p & 63;
        const float4* s4 = (const float4*)(src + p);
        float4 q0 = s4[0], q1 = s4[1], q2 = s4[2], q3 = s4[3];
        float* d = &sp[h + 1][w + 1];
        d[0] = q0.x; d[1] = q0.y; d[2] = q0.z; d[3] = q0.w;
        d[4] = q1.x; d[5] = q1.y; d[6] = q1.z; d[7] = q1.w;
        d[8] = q2.x; d[9] = q2.y; d[10] = q2.z; d[11] = q2.w;
        d[12] = q3.x; d[13] = q3.y; d[14] = q3.z; d[15] = q3.w;
    }
    __syncthreads();
    int h = tid >> 2, xb = (tid & 3) * 16;
    float r0[20], r1[20], r2[20];
    #pragma unroll
    for (int k = 0; k < 5; k++) {
        *(float4*)&r0[k * 4] = *(const float4*)&sp[h + 0][xb + k * 4];
        *(float4*)&r1[k * 4] = *(const float4*)&sp[h + 1][xb + k * 4];
        *(float4*)&r2[k * 4] = *(const float4*)&sp[h + 2][xb + k * 4];
    }
    float acc[16];
    #pragma unroll
    for (int j = 0; j < 16; j++) {
        float a = r1[j + 1];
        a += wk[0] * r0[j];     a += wk[1] * r0[j + 1]; a += wk[2] * r0[j + 2];
        a += wk[3] * r1[j];     a += wk[4] * r1[j + 1]; a += wk[5] * r1[j + 2];
        a += wk[6] * r2[j];     a += wk[7] * r2[j + 1]; a += wk[8] * r2[j + 2];
        acc[j] = a;
    }
    int p = tid * 16;
    if (phase) {
        #pragma unroll
        for (int k = 0; k < 4; k++)
            *(float4*)&dst[p + k * 4] = make_float4(acc[k*4], acc[k*4+1], acc[k*4+2], acc[k*4+3]);
    } else {
        float psum = 0.f;
        #pragma unroll
        for (int j = 0; j < 16; j++) { acc[j] = fmaxf(acc[j], 0.f); psum += acc[j]; }
        #pragma unroll
        for (int k = 0; k < 4; k++)
            *(float4*)&dst[p + k * 4] = make_float4(acc[k*4], acc[k*4+1], acc[k*4+2], acc[k*4+3]);
        for (int off = 16; off; off >>= 1) psum += __shfl_xor_sync(0xffffffffu, psum, off);
        __shared__ float red[8];
        if ((tid & 31) == 0) red[tid >> 5] = psum;
        __syncthreads();
        if (tid < 32) {
            float r = (tid < 8) ? red[tid] : 0.f;
            for (int off = 4; off; off >>= 1) r += __shfl_xor_sync(0xffffffffu, r, off);
            if (tid == 0) g_pool[slot][bc] = r * (1.f / 4096.f);
        }
    }
}

// ---------------- align + weight packing ----------------
__global__ void __launch_bounds__(256, 2) alignweff_kernel(const float* __restrict__ aw,
                                                           const float* __restrict__ w1,
                                                           const float* __restrict__ w2,
                                                           const float* __restrict__ rw1,
                                                           const float* __restrict__ rw2) {
    __shared__ float smem_u[4096];
    int tid = threadIdx.x;
    if (blockIdx.x == 1024) {
        // pack re_w1 -> [tap][16 rows x 64c] sw128, hi|lo
        for (int i = tid; i < 9216; i += 256) {
            int t = i >> 10, rem = i & 1023;
            int row = rem >> 6, c = rem & 63;
            float v = (row < 8) ? rw1[(row * 64 + c) * 9 + t] : 0.f;
            unsigned off = row * 128 + c * 2;
            unsigned sw = off ^ ((off >> 3) & 0x70);
            __nv_bfloat16 hb = __float2bfloat16(v);
            __nv_bfloat16 lb = __float2bfloat16(v - __bfloat162float(hb));
            *(__nv_bfloat16*)(g_w1pack + t * 4096 + sw) = hb;
            *(__nv_bfloat16*)(g_w1pack + t * 4096 + 2048 + sw) = lb;
        }
        return;
    }
    if (blockIdx.x == 1025) {
        // pack re_w2 -> [64 rows x 88 cols (k=t*8+r, pad)] stride 176B, hi|lo
        for (int i = tid; i < 64 * 88; i += 256) {
            int o = i / 88, k = i - o * 88;
            float v = 0.f;
            if (k < 72) { int t = k >> 3, r = k & 7; v = rw2[(o * 8 + r) * 9 + t]; }
            __nv_bfloat16 hb = __float2bfloat16(v);
            __nv_bfloat16 lb = __float2bfloat16(v - __bfloat162float(hb));
            *(__nv_bfloat16*)(g_w2pack + o * 176 + k * 2) = hb;
            *(__nv_bfloat16*)(g_w2pack + 11264 + o * 176 + k * 2) = lb;
        }
        return;
    }
    if (blockIdx.x < 512) {
        // weff -> packed bf16 hi/lo tiles [o(64)][c(64)] SW128
        int sub = blockIdx.x >> 7, ci = blockIdx.x & 127;
        float* s1 = smem_u;
        for (int i = tid; i < 1152; i += 256) {
            int c = i / 9, t = i - c * 9;
            s1[i] = w1[((size_t)(c * 4 + sub) * 128 + ci) * 9 + t];
        }
        __syncthreads();
        if (tid < 64) {
            int o = tid;
            float acc[9] = {0.f,0.f,0.f,0.f,0.f,0.f,0.f,0.f,0.f};
            for (int c = 0; c < 128; c++) {
                float wv = w2[o * 128 + c];
                #pragma unroll
                for (int t = 0; t < 9; t++) acc[t] += wv * s1[c * 9 + t];
            }
            int g = ci >> 6, cl = ci & 63;
            unsigned off = ((o >> 3) << 10) + ((o & 7) << 7) + (cl << 1);
            unsigned sw = off ^ ((off >> 3) & 0x70);
            #pragma unroll
            for (int t = 0; t < 9; t++) {
                float v = acc[t];
                __nv_bfloat16 hb = __float2bfloat16(v);
                __nv_bfloat16 lb = __float2bfloat16(v - __bfloat162float(hb));
                unsigned char* base = g_wpack + ((size_t)((t * 2 + g) * 8 + sub * 2)) * 8192;
                *(__nv_bfloat16*)(base + sw) = hb;
                *(__nv_bfloat16*)(base + 8192 + sw) = lb;
            }
        }
        return;
    }
    // align: fused = concat(a,b) @ aw^T -> g_fu transposed + packed bf16 hi/lo
    int idx = blockIdx.x - 512;
    int q = idx & 3, og = (idx >> 2) & 7, b = idx >> 5;
    float (*sw_s)[16] = (float (*)[16])smem_u;
    for (int i = tid; i < 4096; i += 256) {
        int c = i >> 4, oo = i & 15;
        sw_s[c][oo] = aw[(og * 16 + oo) * 256 + c];
    }
    __syncthreads();
    int pix = q * 1024 + tid * 4;
    const float* ap = &g_ab[0][(size_t)b * CH * PLANE] + pix;
    const float* bp = &g_ab[1][(size_t)b * CH * PLANE] + pix;
    ull acc2[8][4];
    #pragma unroll
    for (int jo = 0; jo < 8; jo++)
        #pragma unroll
        for (int p = 0; p < 4; p++) acc2[jo][p] = 0ull;
    for (int c = 0; c < 128; c++) {
        float4 xv = *(const float4*)(ap + (size_t)c * PLANE);
        ull s0 = splat2(xv.x), s1 = splat2(xv.y), s2 = splat2(xv.z), s3 = splat2(xv.w);
        const ull* wp = (const ull*)&sw_s[c][0];
        #pragma unroll
        for (int jo = 0; jo < 8; jo++) {
            ull wv = wp[jo];
            ffma2(acc2[jo][0], s0, wv); ffma2(acc2[jo][1], s1, wv);
            ffma2(acc2[jo][2], s2, wv); ffma2(acc2[jo][3], s3, wv);
        }
    }
    for (int c = 0; c < 128; c++) {
        float4 xv = *(const float4*)(bp + (size_t)c * PLANE);
        ull s0 = splat2(xv.x), s1 = splat2(xv.y), s2 = splat2(xv.z), s3 = splat2(xv.w);
        const ull* wp = (const ull*)&sw_s[128 + c][0];
        #pragma unroll
        for (int jo = 0; jo < 8; jo++) {
            ull wv = wp[jo];
            ffma2(acc2[jo][0], s0, wv); ffma2(acc2[jo][1], s1, wv);
            ffma2(acc2[jo][2], s2, wv); ffma2(acc2[jo][3], s3, wv);
        }
    }
    unsigned* fb = g_fu + (size_t)b * PLANE * CH;
    #pragma unroll
    for (int p = 0; p < 4; p++) {
        unsigned wbuf[16];
        #pragma unroll
        for (int jo = 0; jo < 8; jo++) {
            float2 v = unpk(acc2[jo][p]);
            wbuf[2*jo]   = packbf(v.x);
            wbuf[2*jo+1] = packbf(v.y);
        }
        unsigned* dstw = fb + (size_t)(pix + p) * CH + og * 16;
        #pragma unroll
        for (int k = 0; k < 4; k++)
            *(uint4*)(dstw + k * 4) = *(uint4*)(wbuf + k * 4);
    }
}

// ---------------- upconv via mma.sync bf16 split --------------------------------
#define UPC_BUF 98304
#define UPC_SMEM (2 * UPC_BUF + 1024)
__global__ void __launch_bounds__(256, 1) upconv_mma(float* __restrict__ out) {
    extern __shared__ char dynraw[];
    char* base = (char*)((((uintptr_t)dynraw) + 1023) & ~(uintptr_t)1023);
    int tid = threadIdx.x;
    int w = tid >> 5, lane = tid & 31;
    int b = blockIdx.x >> 5;
    int y0 = (blockIdx.x & 31) * 2;

    const unsigned* fb = g_fu + (size_t)b * PLANE * CH;
    int m = tid >> 1, half = tid & 1;
    int mrow = m >> 6, mx = m & 63;

    float acc[4][8][4];
    #pragma unroll
    for (int s = 0; s < 4; s++)
        #pragma unroll
        for (int nf = 0; nf < 8; nf++)
            #pragma unroll
            for (int r = 0; r < 4; r++) acc[s][nf][r] = 0.f;

    auto fill = [&](int q, int buf) {
        char* bb = base + buf * UPC_BUF;
        int tap = q >> 1, g = q & 1;
        int kh = tap / 3, kw = tap - kh * 3;
        {
            const unsigned char* bsrc = g_wpack + (size_t)q * 65536;
            unsigned bdst = smaddr(bb + 32768);
            #pragma unroll 4
            for (int i = tid; i < 4096; i += 256)
                cp16(bdst + i * 16, bsrc + i * 16);
        }
        {
            int yy = y0 + mrow + kh - 1;
            int xx = mx + kw - 1;
            bool valid = ((unsigned)yy < 64u) && ((unsigned)xx < 64u);
            const uint4* s4 = (const uint4*)(fb + ((size_t)(yy * 64 + xx) * CH + g * 64 + half * 32));
            char* aHi = bb;
            char* aLo = bb + 16384;
            unsigned db = (unsigned)(m * 128 + half * 64);
            #pragma unroll
            for (int j = 0; j < 4; j++) {
                uint4 w0 = make_uint4(0u,0u,0u,0u), w1 = make_uint4(0u,0u,0u,0u);
                if (valid) { w0 = s4[2 * j]; w1 = s4[2 * j + 1]; }
                uint4 hi, lo;
                hi.x = prmt(w0.x, w0.y, 0x7632); hi.y = prmt(w0.z, w0.w, 0x7632);
                hi.z = prmt(w1.x, w1.y, 0x7632); hi.w = prmt(w1.z, w1.w, 0x7632);
                lo.x = prmt(w0.x, w0.y, 0x5410); lo.y = prmt(w0.z, w0.w, 0x5410);
                lo.z = prmt(w1.x, w1.y, 0x5410); lo.w = prmt(w1.z, w1.w, 0x5410);
                unsigned off = db + j * 16;
                unsigned sw = off ^ ((off >> 3) & 0x70);
                *(uint4*)(aHi + sw) = hi;
                *(uint4*)(aLo + sw) = lo;
            }
        }
    };

    fill(0, 0);
    cp_commit(); cp_wait0();
    __syncthreads();

    for (int q = 0; q < 18; q++) {
        int buf = q & 1;
        if (q < 17) { fill(q + 1, buf ^ 1); cp_commit(); }
        char* bb = base + buf * UPC_BUF;
        unsigned aHiB = smaddr(bb), aLoB = smaddr(bb + 16384);
        unsigned bB = smaddr(bb + 32768);
        #pragma unroll
        for (int kf = 0; kf < 4; kf++) {
            unsigned aH[4], aL[4];
            {
                unsigned arow = (unsigned)(16 * w + (lane & 15));
                unsigned aoff = arow * 128 + kf * 32 + ((lane >> 4) << 4);
                unsigned asw = aoff ^ ((aoff >> 3) & 0x70);
                ldsm4(aH, aHiB + asw);
                ldsm4(aL, aLoB + asw);
            }
            #pragma unroll
            for (int s = 0; s < 4; s++) {
                #pragma unroll
                for (int n0g = 0; n0g < 4; n0g++) {
                    unsigned brow = (unsigned)(16 * n0g + (lane & 15));
                    unsigned boff = brow * 128 + kf * 32 + ((lane >> 4) << 4);
                    unsigned bsw = boff ^ ((boff >> 3) & 0x70);
                    unsigned bH[4], bL[4];
                    ldsm4(bH, bB + s * 16384 + bsw);
                    ldsm4(bL, bB + s * 16384 + 8192 + bsw);
                    float* dA = acc[s][2 * n0g];
                    float* dB = acc[s][2 * n0g + 1];
                    mma_bf16(dA, aH, bH[0], bH[2]);
                    mma_bf16(dB, aH, bH[1], bH[3]);
                    mma_bf16(dA, aH, bL[0], bL[2]);
                    mma_bf16(dB, aH, bL[1], bL[3]);
                    mma_bf16(dA, aL, bH[0], bH[2]);
                    mma_bf16(dB, aL, bH[1], bH[3]);
                }
            }
        }
        if (q < 17) cp_wait0();
        __syncthreads();
    }

    // epilogue: pair subs -> float2 out + packed g_upb
    float2* s2 = (float2*)base;   // [128][65] float2
    unsigned* ub = g_upb + (size_t)b * 16384 * 64;
    int m0 = 16 * w + (lane >> 2);
    int ocol = (lane & 3) * 2;
    #pragma unroll
    for (int sp = 0; sp < 2; sp++) {
        __syncthreads();
        #pragma unroll
        for (int nf = 0; nf < 8; nf++) {
            int o = nf * 8 + ocol;
            s2[m0 * 65 + o]         = make_float2(acc[2*sp][nf][0], acc[2*sp+1][nf][0]);
            s2[m0 * 65 + o + 1]     = make_float2(acc[2*sp][nf][1], acc[2*sp+1][nf][1]);
            s2[(m0 + 8) * 65 + o]   = make_float2(acc[2*sp][nf][2], acc[2*sp+1][nf][2]);
            s2[(m0 + 8) * 65 + o+1] = make_float2(acc[2*sp][nf][3], acc[2*sp+1][nf][3]);
        }
        __syncthreads();
        for (int i = tid; i < 8192; i += 256) {
            int mr = i >> 12, o = (i >> 6) & 63, xx = i & 63;
            int y = 2 * (y0 + mr) + sp;
            *(float2*)(out + (((size_t)(b * 64 + o) * 128 + y) * 128 + 2 * xx)) =
                s2[(mr * 64 + xx) * 65 + o];
        }
        for (int i = tid; i < 16384; i += 256) {
            int mr = i >> 13, x2 = (i >> 6) & 127, o = i & 63;
            int y = 2 * (y0 + mr) + sp;
            float2 v = s2[(mr * 64 + (x2 >> 1)) * 65 + o];
            ub[(size_t)(y * 128 + x2) * 64 + o] = packbf((x2 & 1) ? v.y : v.x);
        }
    }
}

// ---------------- reconv1 via mma: tre = relu(conv3x3(up, re_w1)) ---------------
// grid 2048 = 16 b x 128 y; A window resident; N=8
#define RC1_SMEM (49920 + 49920 + 36864 + 1024)
__global__ void __launch_bounds__(256, 1) reconv1_mma() {
    extern __shared__ char dynraw[];
    char* base = (char*)((((uintptr_t)dynraw) + 1023) & ~(uintptr_t)1023);
    char* aHi = base;
    char* aLo = base + 49920;
    char* sB  = base + 99840;
    int tid = threadIdx.x;
    int w = tid >> 5, lane = tid & 31;
    int b = blockIdx.x >> 7;
    int y = blockIdx.x & 127;
    const unsigned* ub = g_upb + (size_t)b * 16384 * 64;

    // B: 9 taps x 4KB
    {
        unsigned bdst = smaddr(sB);
        for (int i = tid; i < 2304; i += 256)
            cp16(bdst + i * 16, g_w1pack + i * 16);
        cp_commit();
    }
    // A window: 3 rows x 130 x-slots x 64 ch, hi/lo
    for (int u = tid; u < 3120; u += 256) {
        int slot = u >> 3, j8 = u & 7;
        int r = slot / 130, xi = slot - r * 130;
        int gy = y + r - 1, gx = xi - 1;
        uint4 w0 = make_uint4(0u,0u,0u,0u), w1 = make_uint4(0u,0u,0u,0u);
        if (((unsigned)gy < 128u) && ((unsigned)gx < 128u)) {
            const uint4* src = (const uint4*)(ub + (size_t)(gy * 128 + gx) * 64 + j8 * 8);
            w0 = src[0]; w1 = src[1];
        }
        uint4 hi, lo;
        hi.x = prmt(w0.x, w0.y, 0x7632); hi.y = prmt(w0.z, w0.w, 0x7632);
        hi.z = prmt(w1.x, w1.y, 0x7632); hi.w = prmt(w1.z, w1.w, 0x7632);
        lo.x = prmt(w0.x, w0.y, 0x5410); lo.y = prmt(w0.z, w0.w, 0x5410);
        lo.z = prmt(w1.x, w1.y, 0x5410); lo.w = prmt(w1.z, w1.w, 0x5410);
        unsigned off = slot * 128 + j8 * 16;
        unsigned sw = off ^ ((off >> 3) & 0x70);
        *(uint4*)(aHi + sw) = hi;
        *(uint4*)(aLo + sw) = lo;
    }
    cp_wait0();
    __syncthreads();

    unsigned aHiB = smaddr(aHi), aLoB = smaddr(aLo), bB = smaddr(sB);
    float d[4] = {0.f, 0.f, 0.f, 0.f};
    int x0 = 16 * w;
    for (int t = 0; t < 9; t++) {
        int kh = t / 3, kw = t - kh * 3;
        int slot = kh * 130 + x0 + (lane & 15) + kw;
        #pragma unroll
        for (int kf = 0; kf < 4; kf++) {
            unsigned aH[4], aL[4], bH[4], bL[4];
            unsigned aoff = (unsigned)(slot * 128 + kf * 32 + ((lane >> 4) << 4));
            unsigned asw = aoff ^ ((aoff >> 3) & 0x70);
            ldsm4(aH, aHiB + asw);
            ldsm4(aL, aLoB + asw);
            unsigned boff = (unsigned)((lane & 15) * 128 + kf * 32 + ((lane >> 4) << 4));
            unsigned bsw = boff ^ ((boff >> 3) & 0x70);
            ldsm4(bH, bB + t * 4096 + bsw);
            ldsm4(bL, bB + t * 4096 + 2048 + bsw);
            mma_bf16(d, aH, bH[0], bH[2]);
            mma_bf16(d, aH, bL[0], bL[2]);
            mma_bf16(d, aL, bH[0], bH[2]);
        }
    }
    // store tre packed
    unsigned* tb = g_treb + ((size_t)b * 16384 + y * 128) * 8;
    int r = lane >> 2, c = (lane & 3) * 2;
    int px = x0 + r;
    tb[px * 8 + c]           = packbf(fmaxf(d[0], 0.f));
    tb[px * 8 + c + 1]       = packbf(fmaxf(d[1], 0.f));
    tb[(px + 8) * 8 + c]     = packbf(fmaxf(d[2], 0.f));
    tb[(px + 8) * 8 + c + 1] = packbf(fmaxf(d[3], 0.f));
}

// ---------------- reconv2 via mma: out += conv3x3(tre, re_w2) -------------------
// grid 2048 = 16 b x 128 y; im2col K=80 (72+pad), 176B rows (no swizzle)
#define RC2_SMEM (12480 + 22528 + 22528 + 22528 + 1024)
__global__ void __launch_bounds__(256, 2) reconv2_mma(float* __restrict__ out) {
    extern __shared__ char dynraw2[];
    char* base = (char*)((((uintptr_t)dynraw2) + 1023) & ~(uintptr_t)1023);
    unsigned* sTre = (unsigned*)base;            // 3*130*8 = 3120 words
    char* aHi = base + 12480;
    char* aLo = base + 12480 + 22528;
    char* sB  = base + 12480 + 45056;
    int tid = threadIdx.x;
    int w = tid >> 5, lane = tid & 31;
    int b = blockIdx.x >> 7;
    int y = blockIdx.x & 127;
    const unsigned* tb = g_treb + (size_t)b * 16384 * 8;

    {
        unsigned bdst = smaddr(sB);
        for (int i = tid; i < 1408; i += 256)
            cp16(bdst + i * 16, g_w2pack + i * 16);
        cp_commit();
    }
    for (int u = tid; u < 780; u += 256) {
        int slot = u >> 1, hf = u & 1;
        int r = slot / 130, xi = slot - r * 130;
        int gy = y + r - 1, gx = xi - 1;
        uint4 v = make_uint4(0u,0u,0u,0u);
        if (((unsigned)gy < 128u) && ((unsigned)gx < 128u))
            v = *((const uint4*)(tb + (size_t)(gy * 128 + gx) * 8) + hf);
        *((uint4*)(sTre + slot * 8) + hf) = v;
    }
    __syncthreads();
    // build im2col: 128 px x 9 taps x 8 ch
    for (int u = tid; u < 1152; u += 256) {
        int x = u / 9, t = u - x * 9;
        int kh = t / 3, kw = t - kh * 3;
        const unsigned* src = sTre + (kh * 130 + x + kw) * 8;
        uint4 w0 = *(const uint4*)src;
        uint4 w1 = *(const uint4*)(src + 4);
        uint4 hi, lo;
        hi.x = prmt(w0.x, w0.y, 0x7632); hi.y = prmt(w0.z, w0.w, 0x7632);
        hi.z = prmt(w1.x, w1.y, 0x7632); hi.w = prmt(w1.z, w1.w, 0x7632);
        lo.x = prmt(w0.x, w0.y, 0x5410); lo.y = prmt(w0.z, w0.w, 0x5410);
        lo.z = prmt(w1.x, w1.y, 0x5410); lo.w = prmt(w1.z, w1.w, 0x5410);
        *(uint4*)(aHi + x * 176 + t * 16) = hi;
        *(uint4*)(aLo + x * 176 + t * 16) = lo;
    }
    for (int u = tid; u < 128; u += 256) {
        uint4 z = make_uint4(0u,0u,0u,0u);
        *(uint4*)(aHi + u * 176 + 144) = z;
        *(uint4*)(aLo + u * 176 + 144) = z;
    }
    cp_wait0();
    __syncthreads();

    unsigned aHiB = smaddr(aHi), aLoB = smaddr(aLo), bB = smaddr(sB);
    float acc[4][2][4];
    #pragma unroll
    for (int g = 0; g < 4; g++)
        #pragma unroll
        for (int nf = 0; nf < 2; nf++)
            #pragma unroll
            for (int r = 0; r < 4; r++) acc[g][nf][r] = 0.f;
    int x0 = 16 * w;
    #pragma unroll
    for (int kf = 0; kf < 5; kf++) {
        unsigned aH[4], aL[4];
        unsigned aoff = (unsigned)((x0 + (lane & 15)) * 176 + kf * 32 + ((lane >> 4) << 4));
        ldsm4(aH, aHiB + aoff);
        ldsm4(aL, aLoB + aoff);
        #pragma unroll
        for (int n0g = 0; n0g < 4; n0g++) {
            unsigned bH[4], bL[4];
            unsigned boff = (unsigned)((16 * n0g + (lane & 15)) * 176 + kf * 32 + ((lane >> 4) << 4));
            ldsm4(bH, bB + boff);
            ldsm4(bL, bB + 11264 + boff);
            float* dA = acc[n0g][0];
            float* dB = acc[n0g][1];
            mma_bf16(dA, aH, bH[0], bH[2]);
            mma_bf16(dB, aH, bH[1], bH[3]);
            mma_bf16(dA, aH, bL[0], bL[2]);
            mma_bf16(dB, aH, bL[1], bL[3]);
            mma_bf16(dA, aL, bH[0], bH[2]);
            mma_bf16(dB, aL, bH[1], bH[3]);
        }
    }
    __syncthreads();
    float* sD = (float*)aHi;   // [128][65]
    {
        int r = lane >> 2, c = (lane & 3) * 2;
        int px = x0 + r;
        #pragma unroll
        for (int n0g = 0; n0g < 4; n0g++)
            #pragma unroll
            for (int nf = 0; nf < 2; nf++) {
                int o = n0g * 16 + nf * 8 + c;
                sD[px * 65 + o]           = acc[n0g][nf][0];
                sD[px * 65 + o + 1]       = acc[n0g][nf][1];
                sD[(px + 8) * 65 + o]     = acc[n0g][nf][2];
                sD[(px + 8) * 65 + o + 1] = acc[n0g][nf][3];
            }
    }
    __syncthreads();
    for (int i = tid; i < 8192; i += 256) {
        int o = i >> 7, x = i & 127;
        out[((size_t)(b * 64 + o) * 128 + y) * 128 + x] += sD[x * 65 + o];
    }
}

// ---------------------------------------------------------------------------
extern "C" void kernel_launch(void* const* d_in, const int* in_sizes, int n_in,
                              void* d_out, int out_size) {
    const float* x1    = (const float*)d_in[0];
    const float* x2    = (const float*)d_in[1];
    const float* d1_w1 = (const float*)d_in[2];
    const float* d1_w2 = (const float*)d_in[3];
    const float* d2_w1 = (const float*)d_in[4];
    const float* d2_w2 = (const float*)d_in[5];
    const float* align_w = (const float*)d_in[6];
    const float* up_w1 = (const float*)d_in[7];
    const float* up_w2 = (const float*)d_in[8];
    const float* re_w1 = (const float*)d_in[9];
    const float* re_w2 = (const float*)d_in[10];
    float* out = (float*)d_out;

    static int smem_set = 0;
    if (!smem_set) {
        cudaFuncSetAttribute(upconv_mma, cudaFuncAttributeMaxDynamicSharedMemorySize, UPC_SMEM);
        cudaFuncSetAttribute(reconv1_mma, cudaFuncAttributeMaxDynamicSharedMemorySize, RC1_SMEM);
        cudaFuncSetAttribute(reconv2_mma, cudaFuncAttributeMaxDynamicSharedMemorySize, RC2_SMEM);
        smem_set = 1;
    }

    poolmlp_kernel<<<32, 256>>>(x1, x2, d1_w1, d1_w2);
    dsc_kernel<<<4096, 256>>>(x1, x2, 0);
    mlp_kernel<<<32, 128>>>(d2_w1, d2_w2);
    dsc_kernel<<<4096, 256>>>(x1, x2, 1);
    alignweff_kernel<<<1026, 256>>>(align_w, up_w1, up_w2, re_w1, re_w2);
    upconv_mma<<<512, 256, UPC_SMEM>>>(out);
    reconv1_mma<<<2048, 256, RC1_SMEM>>>();
    reconv2_mma<<<2048, 256, RC2_SMEM>>>(out);
}